// round 12
// baseline (speedup 1.0000x reference)
#include <cuda_runtime.h>
#include <cuda_bf16.h>
#include <math.h>
#include <stdint.h>

#define BATCH 8
#define DIMC  192
#define C3    576
#define NH    8
#define HD    24
#define IMH   128
#define IMW   128
#define HW    (IMH*IMW)
#define NSPLIT 32
#define KP    576          // K' = 3 * 192 (split-bf16, A-side duplicated)
#define KT64  9            // k-tiles of 64

// ---------------- scratch (static __device__, no allocations) ----------------
static __device__ float g_qkv[BATCH * C3 * HW];                // 1x1 conv output (fp32)
static __device__ float g_dw [BATCH * C3 * HW];                // depthwise out (q,k fp32)
static __device__ float g_attn_part[NSPLIT * BATCH * NH * HD * HD];
static __device__ float g_np[NSPLIT * BATCH * NH * 2 * HD];
static __device__ float g_attn[BATCH * NH * HD * HD];
static __device__ __nv_bfloat16 g_w1[C3 * KP];                 // A' gemm1 [576][576]
static __device__ __nv_bfloat16 g_m2[BATCH * DIMC * KP];       // A' gemm2 [192][576]
static __device__ __nv_bfloat16 g_xhi[BATCH * DIMC * HW];      // X hi plane [c][n]
static __device__ __nv_bfloat16 g_xlo[BATCH * DIMC * HW];      // X lo plane [c][n]
static __device__ __nv_bfloat16 g_vhi[BATCH * DIMC * HW];      // V hi plane [c][n]
static __device__ __nv_bfloat16 g_vlo[BATCH * DIMC * HW];      // V lo plane [c][n]

// ---------------- PTX helpers (sm_80-level only) ----------------
__device__ __forceinline__ uint32_t s2u(const void* p) {
    uint32_t a;
    asm("{ .reg .u64 t; cvta.to.shared.u64 t, %1; cvt.u32.u64 %0, t; }" : "=r"(a) : "l"(p));
    return a;
}
#define CP16(d, s) asm volatile("cp.async.cg.shared.global [%0], [%1], 16;" :: "r"(d), "l"(s))
#define CP_COMMIT() asm volatile("cp.async.commit_group;" ::: "memory")
#define LDSM4(r0, r1, r2, r3, a) \
    asm volatile("ldmatrix.sync.aligned.m8n8.x4.shared.b16 {%0,%1,%2,%3}, [%4];" \
                 : "=r"(r0), "=r"(r1), "=r"(r2), "=r"(r3) : "r"(a))
#define LDSM4T(r0, r1, r2, r3, a) \
    asm volatile("ldmatrix.sync.aligned.m8n8.x4.trans.shared.b16 {%0,%1,%2,%3}, [%4];" \
                 : "=r"(r0), "=r"(r1), "=r"(r2), "=r"(r3) : "r"(a))
#define MMA16816(d, a, b0, b1) \
    asm volatile("mma.sync.aligned.m16n8k16.row.col.f32.bf16.bf16.f32 " \
                 "{%0,%1,%2,%3}, {%4,%5,%6,%7}, {%8,%9}, {%0,%1,%2,%3};" \
                 : "+f"((d)[0]), "+f"((d)[1]), "+f"((d)[2]), "+f"((d)[3]) \
                 : "r"((a)[0]), "r"((a)[1]), "r"((a)[2]), "r"((a)[3]), \
                   "r"(b0), "r"(b1))

__device__ __forceinline__ uint32_t pkbf(float a, float b) {
    return ((uint32_t)__bfloat16_as_ushort(__float2bfloat16(b)) << 16) |
           (uint32_t)__bfloat16_as_ushort(__float2bfloat16(a));
}

// ---------------- HMMA split-bf16 GEMM, BK=64, 3-stage cp.async pipeline ----------
// BM=64, BN=128, BK=64, 128 thr (4 warps 2x2), warp tile 32x64 (16 MMA : 6 LDSM per ks)
#define ASTR  144                   // A smem row stride (64 bf16 = 128B + 16B pad)
#define BSTR  272                   // B smem row stride (128 bf16 + 16B pad)
#define BOFF  (64 * ASTR)           // 9216
#define BUFSZ (BOFF + 64 * BSTR)    // 9216 + 17408 = 26624
#define STAGES 3
#define SMEM_GEMM (STAGES * BUFSZ)  // 79872
__global__ __launch_bounds__(128, 2) void hmma_gemm(
    const __nv_bfloat16* __restrict__ A,
    const __nv_bfloat16* __restrict__ BHI, const __nv_bfloat16* __restrict__ BLO,
    float* __restrict__ C, long sA, long sBp, long sC)
{
    extern __shared__ __align__(16) char smdyn[];
    const uint32_t sb0 = s2u(smdyn);
    const int tid = threadIdx.x, lane = tid & 31, wid = tid >> 5;
    const int n0 = blockIdx.x << 7;
    const int m0 = blockIdx.y << 6;
    const __nv_bfloat16* Ab  = A   + (long)blockIdx.z * sA;
    const __nv_bfloat16* Bhi = BHI + (long)blockIdx.z * sBp;
    const __nv_bfloat16* Blo = BLO + (long)blockIdx.z * sBp;
    float* Cb = C + (long)blockIdx.z * sC;

    const int wm = (wid >> 1) << 5;     // 0 / 32
    const int wn = (wid & 1) << 6;      // 0 / 64

    float acc[2][8][4];
#pragma unroll
    for (int i = 0; i < 2; i++)
#pragma unroll
        for (int j = 0; j < 8; j++)
#pragma unroll
            for (int v = 0; v < 4; v++) acc[i][j][v] = 0.f;

    const int a_r  = (lane & 7) + ((lane >> 3) & 1) * 8;
    const int a_ko = (lane >> 4) * 16;
    const int bt_k = (lane & 7) + (((lane >> 3) & 1) << 3);
    const int bt_n = (lane >> 4) * 16;

    auto load_tile = [&](int tn, uint32_t db) {
        int pl = tn / 3;                           // 0,1,2 -> hi,lo,hi
        const __nv_bfloat16* Bp = (pl == 1) ? Blo : Bhi;
        int krow0 = (tn - pl * 3) * 64;
        long k0 = (long)tn * 64;
        // A: 64 rows x 8 segs of 16B = 512 chunks, 128 thr -> 4 iters
#pragma unroll
        for (int it = 0; it < 4; it++) {
            int row = (tid >> 3) + it * 16, seg = tid & 7;
            CP16(db + row * ASTR + seg * 16,
                 Ab + (long)(m0 + row) * KP + k0 + seg * 8);
        }
        // B: 64 rows x 16 segs of 16B = 1024 chunks, 128 thr -> 8 iters
#pragma unroll
        for (int it = 0; it < 8; it++) {
            int row = (tid >> 4) + it * 8, seg = tid & 15;
            CP16(db + BOFF + row * BSTR + seg * 16,
                 Bp + (long)(krow0 + row) * HW + n0 + seg * 8);
        }
    };

    // prologue: stages 0..1
    load_tile(0, sb0);
    CP_COMMIT();
    load_tile(1, sb0 + BUFSZ);
    CP_COMMIT();

#pragma unroll
    for (int t = 0; t < KT64; t++) {
        asm volatile("cp.async.wait_group 1;" ::: "memory");
        __syncthreads();
        if (t + 2 < KT64)
            load_tile(t + 2, sb0 + ((t + 2) % STAGES) * BUFSZ);
        CP_COMMIT();   // keep group count fixed

        const uint32_t ab = sb0 + (t % STAGES) * BUFSZ;
        const uint32_t bb = ab + BOFF;
#pragma unroll
        for (int ks = 0; ks < 4; ks++) {
            uint32_t ar[2][4], brT[4][4];
#pragma unroll
            for (int i = 0; i < 2; i++)
                LDSM4(ar[i][0], ar[i][1], ar[i][2], ar[i][3],
                      ab + (wm + i * 16 + a_r) * ASTR + ks * 32 + a_ko);
#pragma unroll
            for (int j = 0; j < 4; j++)
                LDSM4T(brT[j][0], brT[j][1], brT[j][2], brT[j][3],
                       bb + (ks * 16 + bt_k) * BSTR + wn * 2 + j * 32 + bt_n);
#pragma unroll
            for (int i = 0; i < 2; i++)
#pragma unroll
                for (int jn = 0; jn < 8; jn++) {
                    int jj = jn >> 1, pr = jn & 1;
                    MMA16816(acc[i][jn], ar[i], brT[jj][pr * 2], brT[jj][pr * 2 + 1]);
                }
        }
    }

#pragma unroll
    for (int i = 0; i < 2; i++) {
#pragma unroll
        for (int jn = 0; jn < 8; jn++) {
            int r = m0 + wm + i * 16 + (lane >> 2);
            int cc = n0 + wn + jn * 8 + 2 * (lane & 3);
            float2 v0 = make_float2(acc[i][jn][0], acc[i][jn][1]);
            float2 v1 = make_float2(acc[i][jn][2], acc[i][jn][3]);
            *(float2*)(Cb + (long)r * HW + cc)       = v0;
            *(float2*)(Cb + (long)(r + 8) * HW + cc) = v1;
        }
    }
}

// ---------------- split X into bf16 hi/lo planes (same [c][n] layout) ----------------
__global__ __launch_bounds__(256) void splitX_k(const float* __restrict__ src,
                                                __nv_bfloat16* __restrict__ dhi,
                                                __nv_bfloat16* __restrict__ dlo)
{
    long i4 = ((long)blockIdx.x * 256 + threadIdx.x) << 2;
    float4 v = *(const float4*)(src + i4);
    float hx = __bfloat162float(__float2bfloat16(v.x));
    float hy = __bfloat162float(__float2bfloat16(v.y));
    float hz = __bfloat162float(__float2bfloat16(v.z));
    float hw_ = __bfloat162float(__float2bfloat16(v.w));
    uint2 ph = make_uint2(pkbf(v.x, v.y), pkbf(v.z, v.w));
    uint2 pl = make_uint2(pkbf(v.x - hx, v.y - hy), pkbf(v.z - hz, v.w - hw_));
    *(uint2*)(dhi + i4) = ph;
    *(uint2*)(dlo + i4) = pl;
}

// ---------------- split A-side: src fp32 [Msrc][192] -> dst bf16 [Msrc][576] (hi|hi|lo) ------
__global__ __launch_bounds__(256) void splitA_k(const float* __restrict__ src,
                                                __nv_bfloat16* __restrict__ dst,
                                                int Msrc, long sSrc, long sDst)
{
    int b = blockIdx.y;
    int idx = blockIdx.x * 256 + threadIdx.x;
    int m = idx / KP, k = idx - m * KP;
    int sel = k / 192, cc = k - sel * 192;
    __nv_bfloat16 o = __float2bfloat16(0.f);
    if (m < Msrc) {
        float v = src[(long)b * sSrc + (long)m * 192 + cc];
        __nv_bfloat16 hi = __float2bfloat16(v);
        o = (sel < 2) ? hi : __float2bfloat16(v - __bfloat162float(hi));
    }
    dst[(long)b * sDst + idx] = o;
}

// ---------------- depthwise 3x3 tiled: 2 output rows x 4 cols per thread --------------------
__global__ __launch_bounds__(256) void dwconv_k(const float* __restrict__ wdw)
{
    __shared__ float s[18][128];
    int blk   = blockIdx.x;
    int strip = blk & 7;                    // 8 strips of 16 rows
    long bc   = blk >> 3;                   // b*C3 + ch
    int ch    = (int)(bc % C3);
    int b     = (int)(bc / C3);
    const float* in = g_qkv + (bc << 14);
    const int tid = threadIdx.x;

    float w[9];
#pragma unroll
    for (int i = 0; i < 9; i++) w[i] = __ldg(wdw + ch * 9 + i);

    const int y0 = strip << 4;
    for (int i = tid; i < 576; i += 256) {  // 18 rows x 32 float4
        int r = i >> 5, c4 = (i & 31) << 2;
        int gy = y0 - 1 + r;
        float4 v = (gy >= 0 && gy < IMH)
                     ? *(const float4*)(in + gy * IMW + c4)
                     : make_float4(0.f, 0.f, 0.f, 0.f);
        *(float4*)&s[r][c4] = v;
    }
    __syncthreads();

    const int ty = (tid >> 5) << 1;         // 0,2,..,14
    const int x0 = (tid & 31) << 2;
    float o0[4] = {0.f, 0.f, 0.f, 0.f};
    float o1[4] = {0.f, 0.f, 0.f, 0.f};
#pragma unroll
    for (int r = 0; r < 4; r++) {
        const float* sr = s[ty + r];
        float vm = (x0 > 0)   ? sr[x0 - 1] : 0.f;
        float v0 = sr[x0],     v1 = sr[x0 + 1];
        float v2 = sr[x0 + 2], v3 = sr[x0 + 3];
        float vp = (x0 < 124) ? sr[x0 + 4] : 0.f;
        if (r < 3) {
            float wa = w[r * 3], wb = w[r * 3 + 1], wc = w[r * 3 + 2];
            o0[0] = fmaf(wa, vm, fmaf(wb, v0, fmaf(wc, v1, o0[0])));
            o0[1] = fmaf(wa, v0, fmaf(wb, v1, fmaf(wc, v2, o0[1])));
            o0[2] = fmaf(wa, v1, fmaf(wb, v2, fmaf(wc, v3, o0[2])));
            o0[3] = fmaf(wa, v2, fmaf(wb, v3, fmaf(wc, vp, o0[3])));
        }
        if (r >= 1) {
            float wa = w[(r - 1) * 3], wb = w[(r - 1) * 3 + 1], wc = w[(r - 1) * 3 + 2];
            o1[0] = fmaf(wa, vm, fmaf(wb, v0, fmaf(wc, v1, o1[0])));
            o1[1] = fmaf(wa, v0, fmaf(wb, v1, fmaf(wc, v2, o1[1])));
            o1[2] = fmaf(wa, v1, fmaf(wb, v2, fmaf(wc, v3, o1[2])));
            o1[3] = fmaf(wa, v2, fmaf(wb, v3, fmaf(wc, vp, o1[3])));
        }
    }
    int sp0 = (y0 + ty) * IMW + x0;
    int sp1 = sp0 + IMW;
    if (ch < 2 * DIMC) {
        float* op = g_dw + (bc << 14);
        *(float4*)(op + sp0) = make_float4(o0[0], o0[1], o0[2], o0[3]);
        *(float4*)(op + sp1) = make_float4(o1[0], o1[1], o1[2], o1[3]);
    } else {
        long voff = ((long)b * DIMC + (ch - 2 * DIMC)) * HW;
        float h00 = __bfloat162float(__float2bfloat16(o0[0]));
        float h01 = __bfloat162float(__float2bfloat16(o0[1]));
        float h02 = __bfloat162float(__float2bfloat16(o0[2]));
        float h03 = __bfloat162float(__float2bfloat16(o0[3]));
        float h10 = __bfloat162float(__float2bfloat16(o1[0]));
        float h11 = __bfloat162float(__float2bfloat16(o1[1]));
        float h12 = __bfloat162float(__float2bfloat16(o1[2]));
        float h13 = __bfloat162float(__float2bfloat16(o1[3]));
        *(uint2*)(g_vhi + voff + sp0) = make_uint2(pkbf(o0[0], o0[1]), pkbf(o0[2], o0[3]));
        *(uint2*)(g_vhi + voff + sp1) = make_uint2(pkbf(o1[0], o1[1]), pkbf(o1[2], o1[3]));
        *(uint2*)(g_vlo + voff + sp0) = make_uint2(pkbf(o0[0] - h00, o0[1] - h01),
                                                   pkbf(o0[2] - h02, o0[3] - h03));
        *(uint2*)(g_vlo + voff + sp1) = make_uint2(pkbf(o1[0] - h10, o1[1] - h11),
                                                   pkbf(o1[2] - h12, o1[3] - h13));
    }
}

// ---------------- attn partials, 2x3 register-blocked, 96 threads (3 warps exactly) ---------
__global__ __launch_bounds__(96) void attnpart_k()
{
    int bh = blockIdx.x;
    int split = blockIdx.y;
    int b = bh >> 3, h = bh & 7;
    const int tid = threadIdx.x;            // 0..95
    const int cb = tid >> 3, db = tid & 7;  // 12 x 8 blocks
    const int c0 = cb << 1, d0 = db * 3;    // 2 q-rows, 3 k-rows
    __shared__ float qs[24 * 68];
    __shared__ float ks[24 * 68];
    const float* qbase = g_dw + ((long)b * C3 + h * HD) * HW;
    const float* kbase = qbase + (long)DIMC * HW;
    float4 a_[2][3];
#pragma unroll
    for (int i = 0; i < 2; i++)
#pragma unroll
        for (int j = 0; j < 3; j++) a_[i][j] = make_float4(0.f, 0.f, 0.f, 0.f);
    float4 qq[2] = {{0,0,0,0}, {0,0,0,0}};
    float4 kk[3] = {{0,0,0,0}, {0,0,0,0}, {0,0,0,0}};
    const bool doq = (db == 0), dok = (cb == 0);
    int n0 = split * (HW / NSPLIT);
    int n1 = n0 + (HW / NSPLIT);
    for (; n0 < n1; n0 += 64) {
        for (int i = tid; i < 768; i += 96) {
            int m = (i >= 384);
            int j = i - (m ? 384 : 0);
            int r = j >> 4, c4 = j & 15;
            const float* src = (m ? kbase : qbase) + (long)r * HW + n0 + (c4 << 2);
            float* dst = (m ? ks : qs) + r * 68 + (c4 << 2);
            *(float4*)dst = *(const float4*)src;
        }
        __syncthreads();
#pragma unroll
        for (int j = 0; j < 16; j++) {
            float4 q0 = *(const float4*)&qs[ c0      * 68 + (j << 2)];
            float4 q1 = *(const float4*)&qs[(c0 + 1) * 68 + (j << 2)];
            float4 k0 = *(const float4*)&ks[ d0      * 68 + (j << 2)];
            float4 k1 = *(const float4*)&ks[(d0 + 1) * 68 + (j << 2)];
            float4 k2 = *(const float4*)&ks[(d0 + 2) * 68 + (j << 2)];
            float4 qv[2] = {q0, q1};
            float4 kv[3] = {k0, k1, k2};
#pragma unroll
            for (int i = 0; i < 2; i++)
#pragma unroll
                for (int jj = 0; jj < 3; jj++) {
                    a_[i][jj].x = fmaf(qv[i].x, kv[jj].x, a_[i][jj].x);
                    a_[i][jj].y = fmaf(qv[i].y, kv[jj].y, a_[i][jj].y);
                    a_[i][jj].z = fmaf(qv[i].z, kv[jj].z, a_[i][jj].z);
                    a_[i][jj].w = fmaf(qv[i].w, kv[jj].w, a_[i][jj].w);
                }
            if (doq) {
#pragma unroll
                for (int i = 0; i < 2; i++) {
                    qq[i].x = fmaf(qv[i].x, qv[i].x, qq[i].x);
                    qq[i].y = fmaf(qv[i].y, qv[i].y, qq[i].y);
                    qq[i].z = fmaf(qv[i].z, qv[i].z, qq[i].z);
                    qq[i].w = fmaf(qv[i].w, qv[i].w, qq[i].w);
                }
            }
            if (dok) {
#pragma unroll
                for (int jj = 0; jj < 3; jj++) {
                    kk[jj].x = fmaf(kv[jj].x, kv[jj].x, kk[jj].x);
                    kk[jj].y = fmaf(kv[jj].y, kv[jj].y, kk[jj].y);
                    kk[jj].z = fmaf(kv[jj].z, kv[jj].z, kk[jj].z);
                    kk[jj].w = fmaf(kv[jj].w, kv[jj].w, kk[jj].w);
                }
            }
        }
        __syncthreads();
    }
    long pbase = ((long)split * 64 + bh);
    float* ap = g_attn_part + pbase * 576;
#pragma unroll
    for (int i = 0; i < 2; i++)
#pragma unroll
        for (int jj = 0; jj < 3; jj++)
            ap[(c0 + i) * 24 + d0 + jj] =
                (a_[i][jj].x + a_[i][jj].y) + (a_[i][jj].z + a_[i][jj].w);
    float* np = g_np + pbase * 48;
    if (doq) {
        np[c0]     = (qq[0].x + qq[0].y) + (qq[0].z + qq[0].w);
        np[c0 + 1] = (qq[1].x + qq[1].y) + (qq[1].z + qq[1].w);
    }
    if (dok) {
#pragma unroll
        for (int jj = 0; jj < 3; jj++)
            np[24 + d0 + jj] = (kk[jj].x + kk[jj].y) + (kk[jj].z + kk[jj].w);
    }
}

// ---------------- combine splits + norms, scale, softmax ----------------
__global__ __launch_bounds__(576) void softmax_k(const float* __restrict__ temp)
{
    int bh = blockIdx.x; int h = bh & 7;
    int tid = threadIdx.x;
    int c = tid / 24, d = tid - c * 24;
    float s = 0.f;
#pragma unroll
    for (int sp = 0; sp < NSPLIT; sp++)
        s += g_attn_part[((long)sp * 64 + bh) * 576 + tid];
    __shared__ float sinv[48];
    if (tid < 48) {
        float t = 0.f;
#pragma unroll
        for (int sp = 0; sp < NSPLIT; sp++)
            t += g_np[((long)sp * 64 + bh) * 48 + tid];
        sinv[tid] = 1.0f / fmaxf(sqrtf(t), 1e-12f);
    }
    __syncthreads();
    __shared__ float as_[24][25];
    as_[c][d] = s * sinv[c] * sinv[24 + d] * temp[h];
    __syncthreads();
    __shared__ float rowmax[24], rowsum[24];
    if (tid < 24) {
        float m = -1e30f;
#pragma unroll
        for (int j = 0; j < 24; j++) m = fmaxf(m, as_[tid][j]);
        float sum = 0.f;
#pragma unroll
        for (int j = 0; j < 24; j++) sum += expf(as_[tid][j] - m);
        rowmax[tid] = m; rowsum[tid] = sum;
    }
    __syncthreads();
    g_attn[(long)bh * 576 + tid] = expf(as_[c][d] - rowmax[c]) / rowsum[c];
}

// ---------------- M_b = W_out * blockdiag(attn_b), emitted directly as bf16 A' (hi|hi|lo) ----
__global__ __launch_bounds__(256) void buildM_k(const float* __restrict__ wout)
{
    int idx = blockIdx.x * 256 + threadIdx.x;   // 0..36863 = o*192 + (h*24+d)
    int b = blockIdx.y;
    int o  = idx / DIMC, kk = idx - o * DIMC;
    int h  = kk / HD,    d  = kk - h * HD;
    const float* wrow = wout + o * DIMC + h * HD;
    const float* arow = g_attn + (long)(b * NH + h) * (HD * HD) + d;
    float s = 0.f;
#pragma unroll
    for (int cc = 0; cc < HD; cc++)
        s = fmaf(wrow[cc], arow[cc * HD], s);
    __nv_bfloat16 hi = __float2bfloat16(s);
    __nv_bfloat16 lo = __float2bfloat16(s - __bfloat162float(hi));
    __nv_bfloat16* dst = g_m2 + (long)b * (DIMC * KP) + (long)o * KP + kk;
    dst[0]   = hi;
    dst[192] = hi;
    dst[384] = lo;
}

// ---------------- launch ----------------
extern "C" void kernel_launch(void* const* d_in, const int* in_sizes, int n_in,
                              void* d_out, int out_size)
{
    const float* x      = (const float*)d_in[0];
    const float* w_qkv  = (const float*)d_in[1];
    const float* w_dw   = (const float*)d_in[2];
    const float* w_out  = (const float*)d_in[3];
    const float* temp   = (const float*)d_in[4];
    float* out = (float*)d_out;

    float *p_qkv;
    __nv_bfloat16 *p_w1, *p_m2, *p_xhi, *p_xlo, *p_vhi, *p_vlo;
    cudaGetSymbolAddress((void**)&p_qkv, g_qkv);
    cudaGetSymbolAddress((void**)&p_w1,  g_w1);
    cudaGetSymbolAddress((void**)&p_m2,  g_m2);
    cudaGetSymbolAddress((void**)&p_xhi, g_xhi);
    cudaGetSymbolAddress((void**)&p_xlo, g_xlo);
    cudaGetSymbolAddress((void**)&p_vhi, g_vhi);
    cudaGetSymbolAddress((void**)&p_vlo, g_vlo);

    cudaFuncSetAttribute(hmma_gemm, cudaFuncAttributeMaxDynamicSharedMemorySize, SMEM_GEMM);

    // 0) A' = [Whi|Whi|Wlo] for gemm1
    splitA_k<<<dim3(C3 * KP / 256, 1), 256>>>(w_qkv, p_w1, C3, 0L, 0L);

    // 1) X -> bf16 hi/lo planes (no transpose needed)
    splitX_k<<<(BATCH * DIMC * HW) / 1024, 256>>>(x, p_xhi, p_xlo);

    // 2) qkv = W_qkv @ X via HMMA split-bf16 (K'=576, BK=64)
    hmma_gemm<<<dim3(HW / 128, C3 / 64, BATCH), 128, SMEM_GEMM>>>(
        p_w1, p_xhi, p_xlo, p_qkv, 0L, (long)DIMC * HW, (long)C3 * HW);

    // 3) depthwise 3x3 (tiled, 2 rows/thread); V channels emit bf16 hi/lo planes
    dwconv_k<<<BATCH * C3 * 8, 256>>>(w_dw);

    // 4) attn partials + fused norms (split-K, deterministic)
    attnpart_k<<<dim3(BATCH * NH, NSPLIT), 96>>>();

    // 5) combine + scale + softmax
    softmax_k<<<BATCH * NH, 576>>>(temp);

    // 6) M_b = W_out * blockdiag(attn_b) -> bf16 A' directly
    buildM_k<<<dim3((DIMC * DIMC) / 256, BATCH), 256>>>(w_out);

    // 7) out = M_b @ V via HMMA
    hmma_gemm<<<dim3(HW / 128, DIMC / 64, BATCH), 128, SMEM_GEMM>>>(
        p_m2, p_vhi, p_vlo, out, (long)DIMC * KP, (long)DIMC * HW, (long)DIMC * HW);
}

// round 13
// speedup vs baseline: 1.0314x; 1.0314x over previous
#include <cuda_runtime.h>
#include <cuda_bf16.h>
#include <math.h>
#include <stdint.h>

#define BATCH 8
#define DIMC  192
#define C3    576
#define NH    8
#define HD    24
#define IMH   128
#define IMW   128
#define HW    (IMH*IMW)
#define NSPLIT 32
#define KP    576          // K' = 3 * 192 (split-bf16, A-side duplicated)
#define KTILES (KP/32)     // 18
#define M1PAD 640          // gemm1 A rows padded to 5*128
#define M2PAD 256          // gemm2 A rows padded to 2*128

// ---------------- scratch (static __device__, zero-initialized) ----------------
static __device__ float g_qkv[BATCH * C3 * HW];                // 1x1 conv output (fp32)
static __device__ float g_dw [BATCH * C3 * HW];                // depthwise out (q,k fp32)
static __device__ float g_attn_part[NSPLIT * BATCH * NH * HD * HD];
static __device__ float g_np[NSPLIT * BATCH * NH * 2 * HD];
static __device__ float g_attn[BATCH * NH * HD * HD];
static __device__ __nv_bfloat16 g_w1[M1PAD * KP];              // A' gemm1 (padded, pad=0)
static __device__ __nv_bfloat16 g_m2[BATCH * M2PAD * KP];      // A' gemm2 (padded, pad=0)
static __device__ __nv_bfloat16 g_xhi[BATCH * DIMC * HW];      // X hi plane [c][n]
static __device__ __nv_bfloat16 g_xlo[BATCH * DIMC * HW];      // X lo plane [c][n]
static __device__ __nv_bfloat16 g_vhi[BATCH * DIMC * HW];      // V hi plane [c][n]
static __device__ __nv_bfloat16 g_vlo[BATCH * DIMC * HW];      // V lo plane [c][n]

// ---------------- PTX helpers (sm_80-level only) ----------------
__device__ __forceinline__ uint32_t s2u(const void* p) {
    uint32_t a;
    asm("{ .reg .u64 t; cvta.to.shared.u64 t, %1; cvt.u32.u64 %0, t; }" : "=r"(a) : "l"(p));
    return a;
}
#define CP16(d, s) asm volatile("cp.async.cg.shared.global [%0], [%1], 16;" :: "r"(d), "l"(s))
#define CP_COMMIT() asm volatile("cp.async.commit_group;" ::: "memory")
#define LDSM4(r0, r1, r2, r3, a) \
    asm volatile("ldmatrix.sync.aligned.m8n8.x4.shared.b16 {%0,%1,%2,%3}, [%4];" \
                 : "=r"(r0), "=r"(r1), "=r"(r2), "=r"(r3) : "r"(a))
#define LDSM4T(r0, r1, r2, r3, a) \
    asm volatile("ldmatrix.sync.aligned.m8n8.x4.trans.shared.b16 {%0,%1,%2,%3}, [%4];" \
                 : "=r"(r0), "=r"(r1), "=r"(r2), "=r"(r3) : "r"(a))
#define MMA16816(d, a, b0, b1) \
    asm volatile("mma.sync.aligned.m16n8k16.row.col.f32.bf16.bf16.f32 " \
                 "{%0,%1,%2,%3}, {%4,%5,%6,%7}, {%8,%9}, {%0,%1,%2,%3};" \
                 : "+f"((d)[0]), "+f"((d)[1]), "+f"((d)[2]), "+f"((d)[3]) \
                 : "r"((a)[0]), "r"((a)[1]), "r"((a)[2]), "r"((a)[3]), \
                   "r"(b0), "r"(b1))

__device__ __forceinline__ uint32_t pkbf(float a, float b) {
    return ((uint32_t)__bfloat16_as_ushort(__float2bfloat16(b)) << 16) |
           (uint32_t)__bfloat16_as_ushort(__float2bfloat16(a));
}

// ---------------- HMMA split-bf16 GEMM, BK=32, 4-stage pipeline, warp tile 64x64 ----------
// BM=128, BN=128, BK=32, 128 thr (4 warps 2x2): per ks 8 LDSM feed 32 MMAs (4:1)
#define ASTR  80                    // A smem row stride (32 bf16 + 16B pad)
#define BSTR  272                   // B smem row stride (128 bf16 + 16B pad)
#define BOFF  (128 * ASTR)          // 10240
#define BUFSZ (BOFF + 32 * BSTR)    // 10240 + 8704 = 18944
#define STAGES 4
#define SMEM_GEMM (STAGES * BUFSZ)  // 75776
__global__ __launch_bounds__(128, 2) void hmma_gemm(
    const __nv_bfloat16* __restrict__ A,
    const __nv_bfloat16* __restrict__ BHI, const __nv_bfloat16* __restrict__ BLO,
    float* __restrict__ C, int Meff, long sA, long sBp, long sC)
{
    extern __shared__ __align__(16) char smdyn[];
    const uint32_t sb0 = s2u(smdyn);
    const int tid = threadIdx.x, lane = tid & 31, wid = tid >> 5;
    const int n0 = blockIdx.x << 7;
    const int m0 = blockIdx.y << 7;
    const __nv_bfloat16* Ab  = A   + (long)blockIdx.z * sA;
    const __nv_bfloat16* Bhi = BHI + (long)blockIdx.z * sBp;
    const __nv_bfloat16* Blo = BLO + (long)blockIdx.z * sBp;
    float* Cb = C + (long)blockIdx.z * sC;

    const int wm = (wid >> 1) << 6;     // 0 / 64
    const int wn = (wid & 1) << 6;      // 0 / 64

    float acc[4][8][4];
#pragma unroll
    for (int i = 0; i < 4; i++)
#pragma unroll
        for (int j = 0; j < 8; j++)
#pragma unroll
            for (int v = 0; v < 4; v++) acc[i][j][v] = 0.f;

    const int a_r  = (lane & 7) + ((lane >> 3) & 1) * 8;
    const int a_ko = (lane >> 4) * 16;
    const int bt_k = (lane & 7) + (((lane >> 3) & 1) << 3);
    const int bt_n = (lane >> 4) * 16;

    auto load_tile = [&](int tn, uint32_t db) {
        int pl = tn / 6;                           // 0,1,2 -> hi,lo,hi
        const __nv_bfloat16* Bp = (pl == 1) ? Blo : Bhi;
        int krow0 = (tn - pl * 6) * 32;
        long k0 = (long)tn * 32;
        // A: 128 rows x 4 segs of 16B = 512 chunks, 128 thr -> 4 iters
#pragma unroll
        for (int it = 0; it < 4; it++) {
            int row = (tid >> 2) + it * 32, seg = tid & 3;
            CP16(db + row * ASTR + seg * 16,
                 Ab + (long)(m0 + row) * KP + k0 + seg * 8);
        }
        // B: 32 rows x 16 segs of 16B = 512 chunks, 128 thr -> 4 iters
#pragma unroll
        for (int it = 0; it < 4; it++) {
            int row = (tid >> 4) + it * 8, seg = tid & 15;
            CP16(db + BOFF + row * BSTR + seg * 16,
                 Bp + (long)(krow0 + row) * HW + n0 + seg * 8);
        }
    };

    // prologue: stages 0..2
#pragma unroll
    for (int t = 0; t < 3; t++) {
        load_tile(t, sb0 + t * BUFSZ);
        CP_COMMIT();
    }

    for (int t = 0; t < KTILES; t++) {
        asm volatile("cp.async.wait_group 2;" ::: "memory");
        __syncthreads();
        if (t + 3 < KTILES)
            load_tile(t + 3, sb0 + ((t + 3) & (STAGES - 1)) * BUFSZ);
        CP_COMMIT();   // keep group count fixed

        const uint32_t ab = sb0 + (t & (STAGES - 1)) * BUFSZ;
        const uint32_t bb = ab + BOFF;
#pragma unroll
        for (int ks = 0; ks < 2; ks++) {
            uint32_t ar[4][4], brT[4][4];
#pragma unroll
            for (int i = 0; i < 4; i++)
                LDSM4(ar[i][0], ar[i][1], ar[i][2], ar[i][3],
                      ab + (wm + i * 16 + a_r) * ASTR + ks * 32 + a_ko);
#pragma unroll
            for (int j = 0; j < 4; j++)
                LDSM4T(brT[j][0], brT[j][1], brT[j][2], brT[j][3],
                       bb + (ks * 16 + bt_k) * BSTR + wn * 2 + j * 32 + bt_n);
#pragma unroll
            for (int i = 0; i < 4; i++)
#pragma unroll
                for (int jn = 0; jn < 8; jn++) {
                    int jj = jn >> 1, pr = jn & 1;
                    MMA16816(acc[i][jn], ar[i], brT[jj][pr * 2], brT[jj][pr * 2 + 1]);
                }
        }
    }

#pragma unroll
    for (int i = 0; i < 4; i++) {
#pragma unroll
        for (int jn = 0; jn < 8; jn++) {
            int r = m0 + wm + i * 16 + (lane >> 2);
            int cc = n0 + wn + jn * 8 + 2 * (lane & 3);
            if (r < Meff) {
                float2 v0 = make_float2(acc[i][jn][0], acc[i][jn][1]);
                *(float2*)(Cb + (long)r * HW + cc) = v0;
            }
            if (r + 8 < Meff) {
                float2 v1 = make_float2(acc[i][jn][2], acc[i][jn][3]);
                *(float2*)(Cb + (long)(r + 8) * HW + cc) = v1;
            }
        }
    }
}

// ---------------- split X into bf16 hi/lo planes (same [c][n] layout) ----------------
__global__ __launch_bounds__(256) void splitX_k(const float* __restrict__ src,
                                                __nv_bfloat16* __restrict__ dhi,
                                                __nv_bfloat16* __restrict__ dlo)
{
    long i4 = ((long)blockIdx.x * 256 + threadIdx.x) << 2;
    float4 v = *(const float4*)(src + i4);
    float hx = __bfloat162float(__float2bfloat16(v.x));
    float hy = __bfloat162float(__float2bfloat16(v.y));
    float hz = __bfloat162float(__float2bfloat16(v.z));
    float hw_ = __bfloat162float(__float2bfloat16(v.w));
    uint2 ph = make_uint2(pkbf(v.x, v.y), pkbf(v.z, v.w));
    uint2 pl = make_uint2(pkbf(v.x - hx, v.y - hy), pkbf(v.z - hz, v.w - hw_));
    *(uint2*)(dhi + i4) = ph;
    *(uint2*)(dlo + i4) = pl;
}

// ---------------- split A-side: src fp32 [Msrc][192] -> dst bf16 (hi|hi|lo) ------
__global__ __launch_bounds__(256) void splitA_k(const float* __restrict__ src,
                                                __nv_bfloat16* __restrict__ dst,
                                                int Msrc, long sSrc, long sDst)
{
    int b = blockIdx.y;
    int idx = blockIdx.x * 256 + threadIdx.x;
    int m = idx / KP, k = idx - m * KP;
    int sel = k / 192, cc = k - sel * 192;
    __nv_bfloat16 o = __float2bfloat16(0.f);
    if (m < Msrc) {
        float v = src[(long)b * sSrc + (long)m * 192 + cc];
        __nv_bfloat16 hi = __float2bfloat16(v);
        o = (sel < 2) ? hi : __float2bfloat16(v - __bfloat162float(hi));
    }
    dst[(long)b * sDst + idx] = o;
}

// ---------------- depthwise 3x3 tiled: 2 output rows x 4 cols per thread --------------------
__global__ __launch_bounds__(256) void dwconv_k(const float* __restrict__ wdw)
{
    __shared__ float s[18][128];
    int blk   = blockIdx.x;
    int strip = blk & 7;                    // 8 strips of 16 rows
    long bc   = blk >> 3;                   // b*C3 + ch
    int ch    = (int)(bc % C3);
    int b     = (int)(bc / C3);
    const float* in = g_qkv + (bc << 14);
    const int tid = threadIdx.x;

    float w[9];
#pragma unroll
    for (int i = 0; i < 9; i++) w[i] = __ldg(wdw + ch * 9 + i);

    const int y0 = strip << 4;
    for (int i = tid; i < 576; i += 256) {  // 18 rows x 32 float4
        int r = i >> 5, c4 = (i & 31) << 2;
        int gy = y0 - 1 + r;
        float4 v = (gy >= 0 && gy < IMH)
                     ? *(const float4*)(in + gy * IMW + c4)
                     : make_float4(0.f, 0.f, 0.f, 0.f);
        *(float4*)&s[r][c4] = v;
    }
    __syncthreads();

    const int ty = (tid >> 5) << 1;         // 0,2,..,14
    const int x0 = (tid & 31) << 2;
    float o0[4] = {0.f, 0.f, 0.f, 0.f};
    float o1[4] = {0.f, 0.f, 0.f, 0.f};
#pragma unroll
    for (int r = 0; r < 4; r++) {
        const float* sr = s[ty + r];
        float vm = (x0 > 0)   ? sr[x0 - 1] : 0.f;
        float v0 = sr[x0],     v1 = sr[x0 + 1];
        float v2 = sr[x0 + 2], v3 = sr[x0 + 3];
        float vp = (x0 < 124) ? sr[x0 + 4] : 0.f;
        if (r < 3) {
            float wa = w[r * 3], wb = w[r * 3 + 1], wc = w[r * 3 + 2];
            o0[0] = fmaf(wa, vm, fmaf(wb, v0, fmaf(wc, v1, o0[0])));
            o0[1] = fmaf(wa, v0, fmaf(wb, v1, fmaf(wc, v2, o0[1])));
            o0[2] = fmaf(wa, v1, fmaf(wb, v2, fmaf(wc, v3, o0[2])));
            o0[3] = fmaf(wa, v2, fmaf(wb, v3, fmaf(wc, vp, o0[3])));
        }
        if (r >= 1) {
            float wa = w[(r - 1) * 3], wb = w[(r - 1) * 3 + 1], wc = w[(r - 1) * 3 + 2];
            o1[0] = fmaf(wa, vm, fmaf(wb, v0, fmaf(wc, v1, o1[0])));
            o1[1] = fmaf(wa, v0, fmaf(wb, v1, fmaf(wc, v2, o1[1])));
            o1[2] = fmaf(wa, v1, fmaf(wb, v2, fmaf(wc, v3, o1[2])));
            o1[3] = fmaf(wa, v2, fmaf(wb, v3, fmaf(wc, vp, o1[3])));
        }
    }
    int sp0 = (y0 + ty) * IMW + x0;
    int sp1 = sp0 + IMW;
    if (ch < 2 * DIMC) {
        float* op = g_dw + (bc << 14);
        *(float4*)(op + sp0) = make_float4(o0[0], o0[1], o0[2], o0[3]);
        *(float4*)(op + sp1) = make_float4(o1[0], o1[1], o1[2], o1[3]);
    } else {
        long voff = ((long)b * DIMC + (ch - 2 * DIMC)) * HW;
        float h00 = __bfloat162float(__float2bfloat16(o0[0]));
        float h01 = __bfloat162float(__float2bfloat16(o0[1]));
        float h02 = __bfloat162float(__float2bfloat16(o0[2]));
        float h03 = __bfloat162float(__float2bfloat16(o0[3]));
        float h10 = __bfloat162float(__float2bfloat16(o1[0]));
        float h11 = __bfloat162float(__float2bfloat16(o1[1]));
        float h12 = __bfloat162float(__float2bfloat16(o1[2]));
        float h13 = __bfloat162float(__float2bfloat16(o1[3]));
        *(uint2*)(g_vhi + voff + sp0) = make_uint2(pkbf(o0[0], o0[1]), pkbf(o0[2], o0[3]));
        *(uint2*)(g_vhi + voff + sp1) = make_uint2(pkbf(o1[0], o1[1]), pkbf(o1[2], o1[3]));
        *(uint2*)(g_vlo + voff + sp0) = make_uint2(pkbf(o0[0] - h00, o0[1] - h01),
                                                   pkbf(o0[2] - h02, o0[3] - h03));
        *(uint2*)(g_vlo + voff + sp1) = make_uint2(pkbf(o1[0] - h10, o1[1] - h11),
                                                   pkbf(o1[2] - h12, o1[3] - h13));
    }
}

// ---------------- attn partials, 2x3 register-blocked, 96 threads (3 warps exactly) ---------
__global__ __launch_bounds__(96) void attnpart_k()
{
    int bh = blockIdx.x;
    int split = blockIdx.y;
    int b = bh >> 3, h = bh & 7;
    const int tid = threadIdx.x;            // 0..95
    const int cb = tid >> 3, db = tid & 7;  // 12 x 8 blocks
    const int c0 = cb << 1, d0 = db * 3;    // 2 q-rows, 3 k-rows
    __shared__ float qs[24 * 68];
    __shared__ float ks[24 * 68];
    const float* qbase = g_dw + ((long)b * C3 + h * HD) * HW;
    const float* kbase = qbase + (long)DIMC * HW;
    float4 a_[2][3];
#pragma unroll
    for (int i = 0; i < 2; i++)
#pragma unroll
        for (int j = 0; j < 3; j++) a_[i][j] = make_float4(0.f, 0.f, 0.f, 0.f);
    float4 qq[2] = {{0,0,0,0}, {0,0,0,0}};
    float4 kk[3] = {{0,0,0,0}, {0,0,0,0}, {0,0,0,0}};
    const bool doq = (db == 0), dok = (cb == 0);
    int n0 = split * (HW / NSPLIT);
    int n1 = n0 + (HW / NSPLIT);
    for (; n0 < n1; n0 += 64) {
        for (int i = tid; i < 768; i += 96) {
            int m = (i >= 384);
            int j = i - (m ? 384 : 0);
            int r = j >> 4, c4 = j & 15;
            const float* src = (m ? kbase : qbase) + (long)r * HW + n0 + (c4 << 2);
            float* dst = (m ? ks : qs) + r * 68 + (c4 << 2);
            *(float4*)dst = *(const float4*)src;
        }
        __syncthreads();
#pragma unroll
        for (int j = 0; j < 16; j++) {
            float4 q0 = *(const float4*)&qs[ c0      * 68 + (j << 2)];
            float4 q1 = *(const float4*)&qs[(c0 + 1) * 68 + (j << 2)];
            float4 k0 = *(const float4*)&ks[ d0      * 68 + (j << 2)];
            float4 k1 = *(const float4*)&ks[(d0 + 1) * 68 + (j << 2)];
            float4 k2 = *(const float4*)&ks[(d0 + 2) * 68 + (j << 2)];
            float4 qv[2] = {q0, q1};
            float4 kv[3] = {k0, k1, k2};
#pragma unroll
            for (int i = 0; i < 2; i++)
#pragma unroll
                for (int jj = 0; jj < 3; jj++) {
                    a_[i][jj].x = fmaf(qv[i].x, kv[jj].x, a_[i][jj].x);
                    a_[i][jj].y = fmaf(qv[i].y, kv[jj].y, a_[i][jj].y);
                    a_[i][jj].z = fmaf(qv[i].z, kv[jj].z, a_[i][jj].z);
                    a_[i][jj].w = fmaf(qv[i].w, kv[jj].w, a_[i][jj].w);
                }
            if (doq) {
#pragma unroll
                for (int i = 0; i < 2; i++) {
                    qq[i].x = fmaf(qv[i].x, qv[i].x, qq[i].x);
                    qq[i].y = fmaf(qv[i].y, qv[i].y, qq[i].y);
                    qq[i].z = fmaf(qv[i].z, qv[i].z, qq[i].z);
                    qq[i].w = fmaf(qv[i].w, qv[i].w, qq[i].w);
                }
            }
            if (dok) {
#pragma unroll
                for (int jj = 0; jj < 3; jj++) {
                    kk[jj].x = fmaf(kv[jj].x, kv[jj].x, kk[jj].x);
                    kk[jj].y = fmaf(kv[jj].y, kv[jj].y, kk[jj].y);
                    kk[jj].z = fmaf(kv[jj].z, kv[jj].z, kk[jj].z);
                    kk[jj].w = fmaf(kv[jj].w, kv[jj].w, kk[jj].w);
                }
            }
        }
        __syncthreads();
    }
    long pbase = ((long)split * 64 + bh);
    float* ap = g_attn_part + pbase * 576;
#pragma unroll
    for (int i = 0; i < 2; i++)
#pragma unroll
        for (int jj = 0; jj < 3; jj++)
            ap[(c0 + i) * 24 + d0 + jj] =
                (a_[i][jj].x + a_[i][jj].y) + (a_[i][jj].z + a_[i][jj].w);
    float* np = g_np + pbase * 48;
    if (doq) {
        np[c0]     = (qq[0].x + qq[0].y) + (qq[0].z + qq[0].w);
        np[c0 + 1] = (qq[1].x + qq[1].y) + (qq[1].z + qq[1].w);
    }
    if (dok) {
#pragma unroll
        for (int jj = 0; jj < 3; jj++)
            np[24 + d0 + jj] = (kk[jj].x + kk[jj].y) + (kk[jj].z + kk[jj].w);
    }
}

// ---------------- combine splits + norms, scale, softmax ----------------
__global__ __launch_bounds__(576) void softmax_k(const float* __restrict__ temp)
{
    int bh = blockIdx.x; int h = bh & 7;
    int tid = threadIdx.x;
    int c = tid / 24, d = tid - c * 24;
    float s = 0.f;
#pragma unroll
    for (int sp = 0; sp < NSPLIT; sp++)
        s += g_attn_part[((long)sp * 64 + bh) * 576 + tid];
    __shared__ float sinv[48];
    if (tid < 48) {
        float t = 0.f;
#pragma unroll
        for (int sp = 0; sp < NSPLIT; sp++)
            t += g_np[((long)sp * 64 + bh) * 48 + tid];
        sinv[tid] = 1.0f / fmaxf(sqrtf(t), 1e-12f);
    }
    __syncthreads();
    __shared__ float as_[24][25];
    as_[c][d] = s * sinv[c] * sinv[24 + d] * temp[h];
    __syncthreads();
    __shared__ float rowmax[24], rowsum[24];
    if (tid < 24) {
        float m = -1e30f;
#pragma unroll
        for (int j = 0; j < 24; j++) m = fmaxf(m, as_[tid][j]);
        float sum = 0.f;
#pragma unroll
        for (int j = 0; j < 24; j++) sum += expf(as_[tid][j] - m);
        rowmax[tid] = m; rowsum[tid] = sum;
    }
    __syncthreads();
    g_attn[(long)bh * 576 + tid] = expf(as_[c][d] - rowmax[c]) / rowsum[c];
}

// ---------------- M_b = W_out * blockdiag(attn_b), emitted directly as bf16 A' (hi|hi|lo) ----
__global__ __launch_bounds__(256) void buildM_k(const float* __restrict__ wout)
{
    int idx = blockIdx.x * 256 + threadIdx.x;   // 0..36863 = o*192 + (h*24+d)
    int b = blockIdx.y;
    int o  = idx / DIMC, kk = idx - o * DIMC;
    int h  = kk / HD,    d  = kk - h * HD;
    const float* wrow = wout + o * DIMC + h * HD;
    const float* arow = g_attn + (long)(b * NH + h) * (HD * HD) + d;
    float s = 0.f;
#pragma unroll
    for (int cc = 0; cc < HD; cc++)
        s = fmaf(wrow[cc], arow[cc * HD], s);
    __nv_bfloat16 hi = __float2bfloat16(s);
    __nv_bfloat16 lo = __float2bfloat16(s - __bfloat162float(hi));
    __nv_bfloat16* dst = g_m2 + (long)b * (M2PAD * KP) + (long)o * KP + kk;
    dst[0]   = hi;
    dst[192] = hi;
    dst[384] = lo;
}

// ---------------- launch ----------------
extern "C" void kernel_launch(void* const* d_in, const int* in_sizes, int n_in,
                              void* d_out, int out_size)
{
    const float* x      = (const float*)d_in[0];
    const float* w_qkv  = (const float*)d_in[1];
    const float* w_dw   = (const float*)d_in[2];
    const float* w_out  = (const float*)d_in[3];
    const float* temp   = (const float*)d_in[4];
    float* out = (float*)d_out;

    float *p_qkv;
    __nv_bfloat16 *p_w1, *p_m2, *p_xhi, *p_xlo, *p_vhi, *p_vlo;
    cudaGetSymbolAddress((void**)&p_qkv, g_qkv);
    cudaGetSymbolAddress((void**)&p_w1,  g_w1);
    cudaGetSymbolAddress((void**)&p_m2,  g_m2);
    cudaGetSymbolAddress((void**)&p_xhi, g_xhi);
    cudaGetSymbolAddress((void**)&p_xlo, g_xlo);
    cudaGetSymbolAddress((void**)&p_vhi, g_vhi);
    cudaGetSymbolAddress((void**)&p_vlo, g_vlo);

    cudaFuncSetAttribute(hmma_gemm, cudaFuncAttributeMaxDynamicSharedMemorySize, SMEM_GEMM);

    // 0) A' = [Whi|Whi|Wlo] for gemm1 (rows 576..639 stay zero)
    splitA_k<<<dim3(C3 * KP / 256, 1), 256>>>(w_qkv, p_w1, C3, 0L, 0L);

    // 1) X -> bf16 hi/lo planes (no transpose needed)
    splitX_k<<<(BATCH * DIMC * HW) / 1024, 256>>>(x, p_xhi, p_xlo);

    // 2) qkv = W_qkv @ X via HMMA split-bf16 (K'=576), BM=128 warp tile 64x64
    hmma_gemm<<<dim3(HW / 128, M1PAD / 128, BATCH), 128, SMEM_GEMM>>>(
        p_w1, p_xhi, p_xlo, p_qkv, C3, 0L, (long)DIMC * HW, (long)C3 * HW);

    // 3) depthwise 3x3 (tiled, 2 rows/thread); V channels emit bf16 hi/lo planes
    dwconv_k<<<BATCH * C3 * 8, 256>>>(w_dw);

    // 4) attn partials + fused norms (split-K, deterministic)
    attnpart_k<<<dim3(BATCH * NH, NSPLIT), 96>>>();

    // 5) combine + scale + softmax
    softmax_k<<<BATCH * NH, 576>>>(temp);

    // 6) M_b = W_out * blockdiag(attn_b) -> bf16 A' directly (rows 192..255 stay zero)
    buildM_k<<<dim3((DIMC * DIMC) / 256, BATCH), 256>>>(w_out);

    // 7) out = M_b @ V via HMMA
    hmma_gemm<<<dim3(HW / 128, M2PAD / 128, BATCH), 128, SMEM_GEMM>>>(
        p_m2, p_vhi, p_vlo, out, DIMC, (long)M2PAD * KP, (long)DIMC * HW, (long)DIMC * HW);
}

// round 14
// speedup vs baseline: 1.0523x; 1.0202x over previous
#include <cuda_runtime.h>
#include <cuda_bf16.h>
#include <math.h>
#include <stdint.h>

#define BATCH 8
#define DIMC  192
#define C3    576
#define NH    8
#define HD    24
#define IMH   128
#define IMW   128
#define HW    (IMH*IMW)
#define NSPLIT 32
#define KP    576          // K' = 3 * 192 (split-bf16, A-side duplicated)
#define KTILES (KP/32)     // 18

// ---------------- scratch (static __device__, zero-initialized) ----------------
static __device__ float g_qkv[BATCH * C3 * HW];                // 1x1 conv output (fp32)
static __device__ float g_dw [BATCH * C3 * HW];                // depthwise out (q,k fp32)
static __device__ float g_attn_part[NSPLIT * BATCH * NH * HD * HD];
static __device__ float g_np[NSPLIT * BATCH * NH * 2 * HD];
static __device__ float g_attn[BATCH * NH * HD * HD];
static __device__ __nv_bfloat16 g_w1[C3 * KP];                 // A' gemm1 [576][576]
static __device__ __nv_bfloat16 g_m2[BATCH * DIMC * KP];       // A' gemm2 [192][576]
static __device__ __nv_bfloat16 g_xhi[BATCH * DIMC * HW];      // X hi plane [c][n]
static __device__ __nv_bfloat16 g_xlo[BATCH * DIMC * HW];      // X lo plane [c][n]
static __device__ __nv_bfloat16 g_vhi[BATCH * DIMC * HW];      // V hi plane [c][n]
static __device__ __nv_bfloat16 g_vlo[BATCH * DIMC * HW];      // V lo plane [c][n]

// ---------------- PTX helpers (sm_80-level only) ----------------
__device__ __forceinline__ uint32_t s2u(const void* p) {
    uint32_t a;
    asm("{ .reg .u64 t; cvta.to.shared.u64 t, %1; cvt.u32.u64 %0, t; }" : "=r"(a) : "l"(p));
    return a;
}
#define CP16(d, s) asm volatile("cp.async.cg.shared.global [%0], [%1], 16;" :: "r"(d), "l"(s))
#define CP_COMMIT() asm volatile("cp.async.commit_group;" ::: "memory")
#define LDSM4(r0, r1, r2, r3, a) \
    asm volatile("ldmatrix.sync.aligned.m8n8.x4.shared.b16 {%0,%1,%2,%3}, [%4];" \
                 : "=r"(r0), "=r"(r1), "=r"(r2), "=r"(r3) : "r"(a))
#define LDSM4T(r0, r1, r2, r3, a) \
    asm volatile("ldmatrix.sync.aligned.m8n8.x4.trans.shared.b16 {%0,%1,%2,%3}, [%4];" \
                 : "=r"(r0), "=r"(r1), "=r"(r2), "=r"(r3) : "r"(a))
#define MMA16816(d, a, b0, b1) \
    asm volatile("mma.sync.aligned.m16n8k16.row.col.f32.bf16.bf16.f32 " \
                 "{%0,%1,%2,%3}, {%4,%5,%6,%7}, {%8,%9}, {%0,%1,%2,%3};" \
                 : "+f"((d)[0]), "+f"((d)[1]), "+f"((d)[2]), "+f"((d)[3]) \
                 : "r"((a)[0]), "r"((a)[1]), "r"((a)[2]), "r"((a)[3]), \
                   "r"(b0), "r"(b1))

__device__ __forceinline__ uint32_t pkbf(float a, float b) {
    return ((uint32_t)__bfloat16_as_ushort(__float2bfloat16(b)) << 16) |
           (uint32_t)__bfloat16_as_ushort(__float2bfloat16(a));
}

// ================= GEMM variant A: BM=128, warp tile 64x64 (4:1 MMA:LDSM) =================
#define ASTR   80                     // A smem row stride (32 bf16 + 16B pad)
#define BSTR   272                    // B smem row stride (128 bf16 + 16B pad)
#define BOFF1  (128 * ASTR)           // 10240
#define BUFSZ1 (BOFF1 + 32 * BSTR)    // 18944
#define SMEM_G1 (4 * BUFSZ1)          // 75776
__global__ __launch_bounds__(128, 2) void hmma128(
    const __nv_bfloat16* __restrict__ A,
    const __nv_bfloat16* __restrict__ BHI, const __nv_bfloat16* __restrict__ BLO,
    float* __restrict__ C, long sA, long sBp, long sC)
{
    extern __shared__ __align__(16) char smdyn[];
    const uint32_t sb0 = s2u(smdyn);
    const int tid = threadIdx.x, lane = tid & 31, wid = tid >> 5;
    const int n0 = blockIdx.x << 7;
    const int m0 = blockIdx.y << 7;
    const __nv_bfloat16* Ab  = A   + (long)blockIdx.z * sA;
    const __nv_bfloat16* Bhi = BHI + (long)blockIdx.z * sBp;
    const __nv_bfloat16* Blo = BLO + (long)blockIdx.z * sBp;
    float* Cb = C + (long)blockIdx.z * sC;

    const int wm = (wid >> 1) << 6;     // 0 / 64
    const int wn = (wid & 1) << 6;      // 0 / 64

    float acc[4][8][4];
#pragma unroll
    for (int i = 0; i < 4; i++)
#pragma unroll
        for (int j = 0; j < 8; j++)
#pragma unroll
            for (int v = 0; v < 4; v++) acc[i][j][v] = 0.f;

    const int a_r  = (lane & 7) + ((lane >> 3) & 1) * 8;
    const int a_ko = (lane >> 4) * 16;
    const int bt_k = (lane & 7) + (((lane >> 3) & 1) << 3);
    const int bt_n = (lane >> 4) * 16;

    auto load_tile = [&](int tn, uint32_t db) {
        int pl = tn / 6;
        const __nv_bfloat16* Bp = (pl == 1) ? Blo : Bhi;
        int krow0 = (tn - pl * 6) * 32;
        long k0 = (long)tn * 32;
#pragma unroll
        for (int it = 0; it < 4; it++) {
            int row = (tid >> 2) + it * 32, seg = tid & 3;
            CP16(db + row * ASTR + seg * 16,
                 Ab + (long)(m0 + row) * KP + k0 + seg * 8);
        }
#pragma unroll
        for (int it = 0; it < 4; it++) {
            int row = (tid >> 4) + it * 8, seg = tid & 15;
            CP16(db + BOFF1 + row * BSTR + seg * 16,
                 Bp + (long)(krow0 + row) * HW + n0 + seg * 8);
        }
    };

#pragma unroll
    for (int t = 0; t < 3; t++) { load_tile(t, sb0 + t * BUFSZ1); CP_COMMIT(); }

    for (int t = 0; t < KTILES; t++) {
        asm volatile("cp.async.wait_group 2;" ::: "memory");
        __syncthreads();
        if (t + 3 < KTILES)
            load_tile(t + 3, sb0 + ((t + 3) & 3) * BUFSZ1);
        CP_COMMIT();

        const uint32_t ab = sb0 + (t & 3) * BUFSZ1;
        const uint32_t bb = ab + BOFF1;
#pragma unroll
        for (int ks = 0; ks < 2; ks++) {
            uint32_t ar[4][4], brT[4][4];
#pragma unroll
            for (int i = 0; i < 4; i++)
                LDSM4(ar[i][0], ar[i][1], ar[i][2], ar[i][3],
                      ab + (wm + i * 16 + a_r) * ASTR + ks * 32 + a_ko);
#pragma unroll
            for (int j = 0; j < 4; j++)
                LDSM4T(brT[j][0], brT[j][1], brT[j][2], brT[j][3],
                       bb + (ks * 16 + bt_k) * BSTR + wn * 2 + j * 32 + bt_n);
#pragma unroll
            for (int i = 0; i < 4; i++)
#pragma unroll
                for (int jn = 0; jn < 8; jn++) {
                    int jj = jn >> 1, pr = jn & 1;
                    MMA16816(acc[i][jn], ar[i], brT[jj][pr * 2], brT[jj][pr * 2 + 1]);
                }
        }
    }

#pragma unroll
    for (int i = 0; i < 4; i++) {
#pragma unroll
        for (int jn = 0; jn < 8; jn++) {
            int r = m0 + wm + i * 16 + (lane >> 2);
            int cc = n0 + wn + jn * 8 + 2 * (lane & 3);
            float2 v0 = make_float2(acc[i][jn][0], acc[i][jn][1]);
            float2 v1 = make_float2(acc[i][jn][2], acc[i][jn][3]);
            *(float2*)(Cb + (long)r * HW + cc)       = v0;
            *(float2*)(Cb + (long)(r + 8) * HW + cc) = v1;
        }
    }
}

// ================= GEMM variant B: BM=64, warp tile 32x64 (2.7:1), R11-proven =================
#define BOFF2  (64 * ASTR)            // 5120
#define BUFSZ2 (BOFF2 + 32 * BSTR)    // 13824
#define SMEM_G2 (4 * BUFSZ2)          // 55296
__global__ __launch_bounds__(128, 3) void hmma64(
    const __nv_bfloat16* __restrict__ A,
    const __nv_bfloat16* __restrict__ BHI, const __nv_bfloat16* __restrict__ BLO,
    float* __restrict__ C, long sA, long sBp, long sC)
{
    extern __shared__ __align__(16) char smdyn[];
    const uint32_t sb0 = s2u(smdyn);
    const int tid = threadIdx.x, lane = tid & 31, wid = tid >> 5;
    const int n0 = blockIdx.x << 7;
    const int m0 = blockIdx.y << 6;
    const __nv_bfloat16* Ab  = A   + (long)blockIdx.z * sA;
    const __nv_bfloat16* Bhi = BHI + (long)blockIdx.z * sBp;
    const __nv_bfloat16* Blo = BLO + (long)blockIdx.z * sBp;
    float* Cb = C + (long)blockIdx.z * sC;

    const int wm = (wid >> 1) << 5;     // 0 / 32
    const int wn = (wid & 1) << 6;      // 0 / 64

    float acc[2][8][4];
#pragma unroll
    for (int i = 0; i < 2; i++)
#pragma unroll
        for (int j = 0; j < 8; j++)
#pragma unroll
            for (int v = 0; v < 4; v++) acc[i][j][v] = 0.f;

    const int a_r  = (lane & 7) + ((lane >> 3) & 1) * 8;
    const int a_ko = (lane >> 4) * 16;
    const int bt_k = (lane & 7) + (((lane >> 3) & 1) << 3);
    const int bt_n = (lane >> 4) * 16;

    auto load_tile = [&](int tn, uint32_t db) {
        int pl = tn / 6;
        const __nv_bfloat16* Bp = (pl == 1) ? Blo : Bhi;
        int krow0 = (tn - pl * 6) * 32;
        long k0 = (long)tn * 32;
#pragma unroll
        for (int it = 0; it < 2; it++) {
            int row = (tid >> 2) + it * 32, seg = tid & 3;
            CP16(db + row * ASTR + seg * 16,
                 Ab + (long)(m0 + row) * KP + k0 + seg * 8);
        }
#pragma unroll
        for (int it = 0; it < 4; it++) {
            int row = (tid >> 4) + it * 8, seg = tid & 15;
            CP16(db + BOFF2 + row * BSTR + seg * 16,
                 Bp + (long)(krow0 + row) * HW + n0 + seg * 8);
        }
    };

#pragma unroll
    for (int t = 0; t < 3; t++) { load_tile(t, sb0 + t * BUFSZ2); CP_COMMIT(); }

    for (int t = 0; t < KTILES; t++) {
        asm volatile("cp.async.wait_group 2;" ::: "memory");
        __syncthreads();
        if (t + 3 < KTILES)
            load_tile(t + 3, sb0 + ((t + 3) & 3) * BUFSZ2);
        CP_COMMIT();

        const uint32_t ab = sb0 + (t & 3) * BUFSZ2;
        const uint32_t bb = ab + BOFF2;
#pragma unroll
        for (int ks = 0; ks < 2; ks++) {
            uint32_t ar[2][4], brT[4][4];
#pragma unroll
            for (int i = 0; i < 2; i++)
                LDSM4(ar[i][0], ar[i][1], ar[i][2], ar[i][3],
                      ab + (wm + i * 16 + a_r) * ASTR + ks * 32 + a_ko);
#pragma unroll
            for (int j = 0; j < 4; j++)
                LDSM4T(brT[j][0], brT[j][1], brT[j][2], brT[j][3],
                       bb + (ks * 16 + bt_k) * BSTR + wn * 2 + j * 32 + bt_n);
#pragma unroll
            for (int i = 0; i < 2; i++)
#pragma unroll
                for (int jn = 0; jn < 8; jn++) {
                    int jj = jn >> 1, pr = jn & 1;
                    MMA16816(acc[i][jn], ar[i], brT[jj][pr * 2], brT[jj][pr * 2 + 1]);
                }
        }
    }

#pragma unroll
    for (int i = 0; i < 2; i++) {
#pragma unroll
        for (int jn = 0; jn < 8; jn++) {
            int r = m0 + wm + i * 16 + (lane >> 2);
            int cc = n0 + wn + jn * 8 + 2 * (lane & 3);
            float2 v0 = make_float2(acc[i][jn][0], acc[i][jn][1]);
            float2 v1 = make_float2(acc[i][jn][2], acc[i][jn][3]);
            *(float2*)(Cb + (long)r * HW + cc)       = v0;
            *(float2*)(Cb + (long)(r + 8) * HW + cc) = v1;
        }
    }
}

// ---------------- split X into bf16 hi/lo planes (same [c][n] layout) ----------------
__global__ __launch_bounds__(256) void splitX_k(const float* __restrict__ src,
                                                __nv_bfloat16* __restrict__ dhi,
                                                __nv_bfloat16* __restrict__ dlo)
{
    long i4 = ((long)blockIdx.x * 256 + threadIdx.x) << 2;
    float4 v = *(const float4*)(src + i4);
    float hx = __bfloat162float(__float2bfloat16(v.x));
    float hy = __bfloat162float(__float2bfloat16(v.y));
    float hz = __bfloat162float(__float2bfloat16(v.z));
    float hw_ = __bfloat162float(__float2bfloat16(v.w));
    uint2 ph = make_uint2(pkbf(v.x, v.y), pkbf(v.z, v.w));
    uint2 pl = make_uint2(pkbf(v.x - hx, v.y - hy), pkbf(v.z - hz, v.w - hw_));
    *(uint2*)(dhi + i4) = ph;
    *(uint2*)(dlo + i4) = pl;
}

// ---------------- split A-side: src fp32 [Msrc][192] -> dst bf16 (hi|hi|lo) ------
__global__ __launch_bounds__(256) void splitA_k(const float* __restrict__ src,
                                                __nv_bfloat16* __restrict__ dst,
                                                int Msrc, long sSrc, long sDst)
{
    int b = blockIdx.y;
    int idx = blockIdx.x * 256 + threadIdx.x;
    int m = idx / KP, k = idx - m * KP;
    int sel = k / 192, cc = k - sel * 192;
    __nv_bfloat16 o = __float2bfloat16(0.f);
    if (m < Msrc) {
        float v = src[(long)b * sSrc + (long)m * 192 + cc];
        __nv_bfloat16 hi = __float2bfloat16(v);
        o = (sel < 2) ? hi : __float2bfloat16(v - __bfloat162float(hi));
    }
    dst[(long)b * sDst + idx] = o;
}

// ---------------- depthwise 3x3 tiled: 2 output rows x 4 cols per thread --------------------
__global__ __launch_bounds__(256) void dwconv_k(const float* __restrict__ wdw)
{
    __shared__ float s[18][128];
    int blk   = blockIdx.x;
    int strip = blk & 7;                    // 8 strips of 16 rows
    long bc   = blk >> 3;                   // b*C3 + ch
    int ch    = (int)(bc % C3);
    int b     = (int)(bc / C3);
    const float* in = g_qkv + (bc << 14);
    const int tid = threadIdx.x;

    float w[9];
#pragma unroll
    for (int i = 0; i < 9; i++) w[i] = __ldg(wdw + ch * 9 + i);

    const int y0 = strip << 4;
    for (int i = tid; i < 576; i += 256) {  // 18 rows x 32 float4
        int r = i >> 5, c4 = (i & 31) << 2;
        int gy = y0 - 1 + r;
        float4 v = (gy >= 0 && gy < IMH)
                     ? *(const float4*)(in + gy * IMW + c4)
                     : make_float4(0.f, 0.f, 0.f, 0.f);
        *(float4*)&s[r][c4] = v;
    }
    __syncthreads();

    const int ty = (tid >> 5) << 1;         // 0,2,..,14
    const int x0 = (tid & 31) << 2;
    float o0[4] = {0.f, 0.f, 0.f, 0.f};
    float o1[4] = {0.f, 0.f, 0.f, 0.f};
#pragma unroll
    for (int r = 0; r < 4; r++) {
        const float* sr = s[ty + r];
        float vm = (x0 > 0)   ? sr[x0 - 1] : 0.f;
        float v0 = sr[x0],     v1 = sr[x0 + 1];
        float v2 = sr[x0 + 2], v3 = sr[x0 + 3];
        float vp = (x0 < 124) ? sr[x0 + 4] : 0.f;
        if (r < 3) {
            float wa = w[r * 3], wb = w[r * 3 + 1], wc = w[r * 3 + 2];
            o0[0] = fmaf(wa, vm, fmaf(wb, v0, fmaf(wc, v1, o0[0])));
            o0[1] = fmaf(wa, v0, fmaf(wb, v1, fmaf(wc, v2, o0[1])));
            o0[2] = fmaf(wa, v1, fmaf(wb, v2, fmaf(wc, v3, o0[2])));
            o0[3] = fmaf(wa, v2, fmaf(wb, v3, fmaf(wc, vp, o0[3])));
        }
        if (r >= 1) {
            float wa = w[(r - 1) * 3], wb = w[(r - 1) * 3 + 1], wc = w[(r - 1) * 3 + 2];
            o1[0] = fmaf(wa, vm, fmaf(wb, v0, fmaf(wc, v1, o1[0])));
            o1[1] = fmaf(wa, v0, fmaf(wb, v1, fmaf(wc, v2, o1[1])));
            o1[2] = fmaf(wa, v1, fmaf(wb, v2, fmaf(wc, v3, o1[2])));
            o1[3] = fmaf(wa, v2, fmaf(wb, v3, fmaf(wc, vp, o1[3])));
        }
    }
    int sp0 = (y0 + ty) * IMW + x0;
    int sp1 = sp0 + IMW;
    if (ch < 2 * DIMC) {
        float* op = g_dw + (bc << 14);
        *(float4*)(op + sp0) = make_float4(o0[0], o0[1], o0[2], o0[3]);
        *(float4*)(op + sp1) = make_float4(o1[0], o1[1], o1[2], o1[3]);
    } else {
        long voff = ((long)b * DIMC + (ch - 2 * DIMC)) * HW;
        float h00 = __bfloat162float(__float2bfloat16(o0[0]));
        float h01 = __bfloat162float(__float2bfloat16(o0[1]));
        float h02 = __bfloat162float(__float2bfloat16(o0[2]));
        float h03 = __bfloat162float(__float2bfloat16(o0[3]));
        float h10 = __bfloat162float(__float2bfloat16(o1[0]));
        float h11 = __bfloat162float(__float2bfloat16(o1[1]));
        float h12 = __bfloat162float(__float2bfloat16(o1[2]));
        float h13 = __bfloat162float(__float2bfloat16(o1[3]));
        *(uint2*)(g_vhi + voff + sp0) = make_uint2(pkbf(o0[0], o0[1]), pkbf(o0[2], o0[3]));
        *(uint2*)(g_vhi + voff + sp1) = make_uint2(pkbf(o1[0], o1[1]), pkbf(o1[2], o1[3]));
        *(uint2*)(g_vlo + voff + sp0) = make_uint2(pkbf(o0[0] - h00, o0[1] - h01),
                                                   pkbf(o0[2] - h02, o0[3] - h03));
        *(uint2*)(g_vlo + voff + sp1) = make_uint2(pkbf(o1[0] - h10, o1[1] - h11),
                                                   pkbf(o1[2] - h12, o1[3] - h13));
    }
}

// ---------------- attn partials, 2x3 register-blocked, 96 threads (3 warps exactly) ---------
__global__ __launch_bounds__(96) void attnpart_k()
{
    int bh = blockIdx.x;
    int split = blockIdx.y;
    int b = bh >> 3, h = bh & 7;
    const int tid = threadIdx.x;            // 0..95
    const int cb = tid >> 3, db = tid & 7;  // 12 x 8 blocks
    const int c0 = cb << 1, d0 = db * 3;    // 2 q-rows, 3 k-rows
    __shared__ float qs[24 * 68];
    __shared__ float ks[24 * 68];
    const float* qbase = g_dw + ((long)b * C3 + h * HD) * HW;
    const float* kbase = qbase + (long)DIMC * HW;
    float4 a_[2][3];
#pragma unroll
    for (int i = 0; i < 2; i++)
#pragma unroll
        for (int j = 0; j < 3; j++) a_[i][j] = make_float4(0.f, 0.f, 0.f, 0.f);
    float4 qq[2] = {{0,0,0,0}, {0,0,0,0}};
    float4 kk[3] = {{0,0,0,0}, {0,0,0,0}, {0,0,0,0}};
    const bool doq = (db == 0), dok = (cb == 0);
    int n0 = split * (HW / NSPLIT);
    int n1 = n0 + (HW / NSPLIT);
    for (; n0 < n1; n0 += 64) {
        for (int i = tid; i < 768; i += 96) {
            int m = (i >= 384);
            int j = i - (m ? 384 : 0);
            int r = j >> 4, c4 = j & 15;
            const float* src = (m ? kbase : qbase) + (long)r * HW + n0 + (c4 << 2);
            float* dst = (m ? ks : qs) + r * 68 + (c4 << 2);
            *(float4*)dst = *(const float4*)src;
        }
        __syncthreads();
#pragma unroll
        for (int j = 0; j < 16; j++) {
            float4 q0 = *(const float4*)&qs[ c0      * 68 + (j << 2)];
            float4 q1 = *(const float4*)&qs[(c0 + 1) * 68 + (j << 2)];
            float4 k0 = *(const float4*)&ks[ d0      * 68 + (j << 2)];
            float4 k1 = *(const float4*)&ks[(d0 + 1) * 68 + (j << 2)];
            float4 k2 = *(const float4*)&ks[(d0 + 2) * 68 + (j << 2)];
            float4 qv[2] = {q0, q1};
            float4 kv[3] = {k0, k1, k2};
#pragma unroll
            for (int i = 0; i < 2; i++)
#pragma unroll
                for (int jj = 0; jj < 3; jj++) {
                    a_[i][jj].x = fmaf(qv[i].x, kv[jj].x, a_[i][jj].x);
                    a_[i][jj].y = fmaf(qv[i].y, kv[jj].y, a_[i][jj].y);
                    a_[i][jj].z = fmaf(qv[i].z, kv[jj].z, a_[i][jj].z);
                    a_[i][jj].w = fmaf(qv[i].w, kv[jj].w, a_[i][jj].w);
                }
            if (doq) {
#pragma unroll
                for (int i = 0; i < 2; i++) {
                    qq[i].x = fmaf(qv[i].x, qv[i].x, qq[i].x);
                    qq[i].y = fmaf(qv[i].y, qv[i].y, qq[i].y);
                    qq[i].z = fmaf(qv[i].z, qv[i].z, qq[i].z);
                    qq[i].w = fmaf(qv[i].w, qv[i].w, qq[i].w);
                }
            }
            if (dok) {
#pragma unroll
                for (int jj = 0; jj < 3; jj++) {
                    kk[jj].x = fmaf(kv[jj].x, kv[jj].x, kk[jj].x);
                    kk[jj].y = fmaf(kv[jj].y, kv[jj].y, kk[jj].y);
                    kk[jj].z = fmaf(kv[jj].z, kv[jj].z, kk[jj].z);
                    kk[jj].w = fmaf(kv[jj].w, kv[jj].w, kk[jj].w);
                }
            }
        }
        __syncthreads();
    }
    long pbase = ((long)split * 64 + bh);
    float* ap = g_attn_part + pbase * 576;
#pragma unroll
    for (int i = 0; i < 2; i++)
#pragma unroll
        for (int jj = 0; jj < 3; jj++)
            ap[(c0 + i) * 24 + d0 + jj] =
                (a_[i][jj].x + a_[i][jj].y) + (a_[i][jj].z + a_[i][jj].w);
    float* np = g_np + pbase * 48;
    if (doq) {
        np[c0]     = (qq[0].x + qq[0].y) + (qq[0].z + qq[0].w);
        np[c0 + 1] = (qq[1].x + qq[1].y) + (qq[1].z + qq[1].w);
    }
    if (dok) {
#pragma unroll
        for (int jj = 0; jj < 3; jj++)
            np[24 + d0 + jj] = (kk[jj].x + kk[jj].y) + (kk[jj].z + kk[jj].w);
    }
}

// ---------------- combine splits + norms, scale, softmax ----------------
__global__ __launch_bounds__(576) void softmax_k(const float* __restrict__ temp)
{
    int bh = blockIdx.x; int h = bh & 7;
    int tid = threadIdx.x;
    int c = tid / 24, d = tid - c * 24;
    float s = 0.f;
#pragma unroll
    for (int sp = 0; sp < NSPLIT; sp++)
        s += g_attn_part[((long)sp * 64 + bh) * 576 + tid];
    __shared__ float sinv[48];
    if (tid < 48) {
        float t = 0.f;
#pragma unroll
        for (int sp = 0; sp < NSPLIT; sp++)
            t += g_np[((long)sp * 64 + bh) * 48 + tid];
        sinv[tid] = 1.0f / fmaxf(sqrtf(t), 1e-12f);
    }
    __syncthreads();
    __shared__ float as_[24][25];
    as_[c][d] = s * sinv[c] * sinv[24 + d] * temp[h];
    __syncthreads();
    __shared__ float rowmax[24], rowsum[24];
    if (tid < 24) {
        float m = -1e30f;
#pragma unroll
        for (int j = 0; j < 24; j++) m = fmaxf(m, as_[tid][j]);
        float sum = 0.f;
#pragma unroll
        for (int j = 0; j < 24; j++) sum += expf(as_[tid][j] - m);
        rowmax[tid] = m; rowsum[tid] = sum;
    }
    __syncthreads();
    g_attn[(long)bh * 576 + tid] = expf(as_[c][d] - rowmax[c]) / rowsum[c];
}

// ---------------- M_b = W_out * blockdiag(attn_b), emitted directly as bf16 A' (hi|hi|lo) ----
__global__ __launch_bounds__(256) void buildM_k(const float* __restrict__ wout)
{
    int idx = blockIdx.x * 256 + threadIdx.x;   // 0..36863 = o*192 + (h*24+d)
    int b = blockIdx.y;
    int o  = idx / DIMC, kk = idx - o * DIMC;
    int h  = kk / HD,    d  = kk - h * HD;
    const float* wrow = wout + o * DIMC + h * HD;
    const float* arow = g_attn + (long)(b * NH + h) * (HD * HD) + d;
    float s = 0.f;
#pragma unroll
    for (int cc = 0; cc < HD; cc++)
        s = fmaf(wrow[cc], arow[cc * HD], s);
    __nv_bfloat16 hi = __float2bfloat16(s);
    __nv_bfloat16 lo = __float2bfloat16(s - __bfloat162float(hi));
    __nv_bfloat16* dst = g_m2 + (long)b * (DIMC * KP) + (long)o * KP + kk;
    dst[0]   = hi;
    dst[192] = hi;
    dst[384] = lo;
}

// ---------------- launch ----------------
extern "C" void kernel_launch(void* const* d_in, const int* in_sizes, int n_in,
                              void* d_out, int out_size)
{
    const float* x      = (const float*)d_in[0];
    const float* w_qkv  = (const float*)d_in[1];
    const float* w_dw   = (const float*)d_in[2];
    const float* w_out  = (const float*)d_in[3];
    const float* temp   = (const float*)d_in[4];
    float* out = (float*)d_out;

    float *p_qkv;
    __nv_bfloat16 *p_w1, *p_m2, *p_xhi, *p_xlo, *p_vhi, *p_vlo;
    cudaGetSymbolAddress((void**)&p_qkv, g_qkv);
    cudaGetSymbolAddress((void**)&p_w1,  g_w1);
    cudaGetSymbolAddress((void**)&p_m2,  g_m2);
    cudaGetSymbolAddress((void**)&p_xhi, g_xhi);
    cudaGetSymbolAddress((void**)&p_xlo, g_xlo);
    cudaGetSymbolAddress((void**)&p_vhi, g_vhi);
    cudaGetSymbolAddress((void**)&p_vlo, g_vlo);

    cudaFuncSetAttribute(hmma128, cudaFuncAttributeMaxDynamicSharedMemorySize, SMEM_G1);
    cudaFuncSetAttribute(hmma64,  cudaFuncAttributeMaxDynamicSharedMemorySize, SMEM_G2);

    // 0) A' = [Whi|Whi|Wlo] for gemm1
    splitA_k<<<dim3(C3 * KP / 256, 1), 256>>>(w_qkv, p_w1, C3, 0L, 0L);

    // 1) X -> bf16 hi/lo planes (no transpose needed)
    splitX_k<<<(BATCH * DIMC * HW) / 1024, 256>>>(x, p_xhi, p_xlo);

    // 2a) qkv rows 0..511 via BM=128 kernel (zero waste, 4:1 mix)
    hmma128<<<dim3(HW / 128, 4, BATCH), 128, SMEM_G1>>>(
        p_w1, p_xhi, p_xlo, p_qkv, 0L, (long)DIMC * HW, (long)C3 * HW);

    // 2b) qkv rows 512..575 via BM=64 kernel (exact tail)
    hmma64<<<dim3(HW / 128, 1, BATCH), 128, SMEM_G2>>>(
        p_w1 + (long)512 * KP, p_xhi, p_xlo, p_qkv + (long)512 * HW,
        0L, (long)DIMC * HW, (long)C3 * HW);

    // 3) depthwise 3x3 (tiled, 2 rows/thread); V channels emit bf16 hi/lo planes
    dwconv_k<<<BATCH * C3 * 8, 256>>>(w_dw);

    // 4) attn partials + fused norms (split-K, deterministic)
    attnpart_k<<<dim3(BATCH * NH, NSPLIT), 96>>>();

    // 5) combine + scale + softmax
    softmax_k<<<BATCH * NH, 576>>>(temp);

    // 6) M_b = W_out * blockdiag(attn_b) -> bf16 A' directly
    buildM_k<<<dim3((DIMC * DIMC) / 256, BATCH), 256>>>(w_out);

    // 7) out = M_b @ V via BM=64 kernel (192 = 3x64, zero waste)
    hmma64<<<dim3(HW / 128, 3, BATCH), 128, SMEM_G2>>>(
        p_m2, p_vhi, p_vlo, out, (long)DIMC * KP, (long)DIMC * HW, (long)DIMC * HW);
}

// round 15
// speedup vs baseline: 1.0600x; 1.0073x over previous
#include <cuda_runtime.h>
#include <cuda_bf16.h>
#include <math.h>
#include <stdint.h>

#define BATCH 8
#define DIMC  192
#define C3    576
#define NH    8
#define HD    24
#define IMH   128
#define IMW   128
#define HW    (IMH*IMW)
#define NSPLIT 32
#define KP    576          // K' = 3 * 192 (split-bf16, A-side duplicated)
#define KTILES (KP/32)     // 18

// ---------------- scratch (static __device__, zero-initialized) ----------------
static __device__ float g_qkv[BATCH * C3 * HW];                // 1x1 conv output (fp32)
static __device__ float g_dw [BATCH * C3 * HW];                // depthwise out (q,k fp32)
static __device__ float g_attn_part[NSPLIT * BATCH * NH * HD * HD];
static __device__ float g_np[NSPLIT * BATCH * NH * 2 * HD];
static __device__ float g_attn[BATCH * NH * HD * HD];
static __device__ __nv_bfloat16 g_w1[C3 * KP];                 // A' gemm1 [576][576]
static __device__ __nv_bfloat16 g_m2[BATCH * DIMC * KP];       // A' gemm2 [192][576]
static __device__ __nv_bfloat16 g_xhi[BATCH * DIMC * HW];      // X hi plane [c][n]
static __device__ __nv_bfloat16 g_xlo[BATCH * DIMC * HW];      // X lo plane [c][n]
static __device__ __nv_bfloat16 g_vhi[BATCH * DIMC * HW];      // V hi plane [c][n]
static __device__ __nv_bfloat16 g_vlo[BATCH * DIMC * HW];      // V lo plane [c][n]

// ---------------- PTX helpers (sm_80-level only) ----------------
__device__ __forceinline__ uint32_t s2u(const void* p) {
    uint32_t a;
    asm("{ .reg .u64 t; cvta.to.shared.u64 t, %1; cvt.u32.u64 %0, t; }" : "=r"(a) : "l"(p));
    return a;
}
#define CP16(d, s) asm volatile("cp.async.cg.shared.global [%0], [%1], 16;" :: "r"(d), "l"(s))
#define CP_COMMIT() asm volatile("cp.async.commit_group;" ::: "memory")
#define LDSM4(r0, r1, r2, r3, a) \
    asm volatile("ldmatrix.sync.aligned.m8n8.x4.shared.b16 {%0,%1,%2,%3}, [%4];" \
                 : "=r"(r0), "=r"(r1), "=r"(r2), "=r"(r3) : "r"(a))
#define LDSM4T(r0, r1, r2, r3, a) \
    asm volatile("ldmatrix.sync.aligned.m8n8.x4.trans.shared.b16 {%0,%1,%2,%3}, [%4];" \
                 : "=r"(r0), "=r"(r1), "=r"(r2), "=r"(r3) : "r"(a))
#define MMA16816(d, a, b0, b1) \
    asm volatile("mma.sync.aligned.m16n8k16.row.col.f32.bf16.bf16.f32 " \
                 "{%0,%1,%2,%3}, {%4,%5,%6,%7}, {%8,%9}, {%0,%1,%2,%3};" \
                 : "+f"((d)[0]), "+f"((d)[1]), "+f"((d)[2]), "+f"((d)[3]) \
                 : "r"((a)[0]), "r"((a)[1]), "r"((a)[2]), "r"((a)[3]), \
                   "r"(b0), "r"(b1))

__device__ __forceinline__ uint32_t pkbf(float a, float b) {
    return ((uint32_t)__bfloat16_as_ushort(__float2bfloat16(b)) << 16) |
           (uint32_t)__bfloat16_as_ushort(__float2bfloat16(a));
}

// ============ merged GEMM: full tiles BM=128 (warp 64x64, 4:1), last tile BM=64 ============
#define ASTR   80                     // A smem row stride (32 bf16 + 16B pad)
#define BSTR   272                    // B smem row stride (128 bf16 + 16B pad)
#define BOFF   (128 * ASTR)           // 10240
#define BUFSZ  (BOFF + 32 * BSTR)     // 18944
#define SMEM_G (4 * BUFSZ)            // 75776
__global__ __launch_bounds__(128, 2) void hmma_gemm(
    const __nv_bfloat16* __restrict__ A,
    const __nv_bfloat16* __restrict__ BHI, const __nv_bfloat16* __restrict__ BLO,
    float* __restrict__ C, int Mtot, long sA, long sBp, long sC)
{
    extern __shared__ __align__(16) char smdyn[];
    const uint32_t sb0 = s2u(smdyn);
    const int tid = threadIdx.x, lane = tid & 31, wid = tid >> 5;
    const int n0 = blockIdx.x << 7;
    const int m0 = blockIdx.y << 7;
    const bool full = (Mtot - m0) >= 128;   // uniform per CTA
    const __nv_bfloat16* Ab  = A   + (long)blockIdx.z * sA;
    const __nv_bfloat16* Bhi = BHI + (long)blockIdx.z * sBp;
    const __nv_bfloat16* Blo = BLO + (long)blockIdx.z * sBp;
    float* Cb = C + (long)blockIdx.z * sC;

    const int a_r  = (lane & 7) + ((lane >> 3) & 1) * 8;
    const int a_ko = (lane >> 4) * 16;
    const int bt_k = (lane & 7) + (((lane >> 3) & 1) << 3);
    const int bt_n = (lane >> 4) * 16;
    const int wn = (wid & 1) << 6;      // 0 / 64 (both paths)

    auto loadB = [&](int tn, uint32_t db) {
        int pl = tn / 6;
        const __nv_bfloat16* Bp = (pl == 1) ? Blo : Bhi;
        int krow0 = (tn - pl * 6) * 32;
#pragma unroll
        for (int it = 0; it < 4; it++) {
            int row = (tid >> 4) + it * 8, seg = tid & 15;
            CP16(db + BOFF + row * BSTR + seg * 16,
                 Bp + (long)(krow0 + row) * HW + n0 + seg * 8);
        }
    };

    if (full) {
        const int wm = (wid >> 1) << 6;     // 0 / 64
        float acc[4][8][4];
#pragma unroll
        for (int i = 0; i < 4; i++)
#pragma unroll
            for (int j = 0; j < 8; j++)
#pragma unroll
                for (int v = 0; v < 4; v++) acc[i][j][v] = 0.f;

        auto load_tile = [&](int tn, uint32_t db) {
            long k0 = (long)tn * 32;
#pragma unroll
            for (int it = 0; it < 4; it++) {
                int row = (tid >> 2) + it * 32, seg = tid & 3;
                CP16(db + row * ASTR + seg * 16,
                     Ab + (long)(m0 + row) * KP + k0 + seg * 8);
            }
            loadB(tn, db);
        };

#pragma unroll
        for (int t = 0; t < 3; t++) { load_tile(t, sb0 + t * BUFSZ); CP_COMMIT(); }

        for (int t = 0; t < KTILES; t++) {
            asm volatile("cp.async.wait_group 2;" ::: "memory");
            __syncthreads();
            if (t + 3 < KTILES)
                load_tile(t + 3, sb0 + ((t + 3) & 3) * BUFSZ);
            CP_COMMIT();

            const uint32_t ab = sb0 + (t & 3) * BUFSZ;
            const uint32_t bb = ab + BOFF;
#pragma unroll
            for (int ks = 0; ks < 2; ks++) {
                uint32_t ar[4][4], brT[4][4];
#pragma unroll
                for (int i = 0; i < 4; i++)
                    LDSM4(ar[i][0], ar[i][1], ar[i][2], ar[i][3],
                          ab + (wm + i * 16 + a_r) * ASTR + ks * 32 + a_ko);
#pragma unroll
                for (int j = 0; j < 4; j++)
                    LDSM4T(brT[j][0], brT[j][1], brT[j][2], brT[j][3],
                           bb + (ks * 16 + bt_k) * BSTR + wn * 2 + j * 32 + bt_n);
#pragma unroll
                for (int i = 0; i < 4; i++)
#pragma unroll
                    for (int jn = 0; jn < 8; jn++) {
                        int jj = jn >> 1, pr = jn & 1;
                        MMA16816(acc[i][jn], ar[i], brT[jj][pr * 2], brT[jj][pr * 2 + 1]);
                    }
            }
        }

#pragma unroll
        for (int i = 0; i < 4; i++) {
#pragma unroll
            for (int jn = 0; jn < 8; jn++) {
                int r = m0 + wm + i * 16 + (lane >> 2);
                int cc = n0 + wn + jn * 8 + 2 * (lane & 3);
                float2 v0 = make_float2(acc[i][jn][0], acc[i][jn][1]);
                float2 v1 = make_float2(acc[i][jn][2], acc[i][jn][3]);
                *(float2*)(Cb + (long)r * HW + cc)       = v0;
                *(float2*)(Cb + (long)(r + 8) * HW + cc) = v1;
            }
        }
    } else {
        // 64-row remainder tile: warp tile 32x64
        const int wm = (wid >> 1) << 5;     // 0 / 32
        float acc[2][8][4];
#pragma unroll
        for (int i = 0; i < 2; i++)
#pragma unroll
            for (int j = 0; j < 8; j++)
#pragma unroll
                for (int v = 0; v < 4; v++) acc[i][j][v] = 0.f;

        auto load_tile = [&](int tn, uint32_t db) {
            long k0 = (long)tn * 32;
#pragma unroll
            for (int it = 0; it < 2; it++) {
                int row = (tid >> 2) + it * 32, seg = tid & 3;
                CP16(db + row * ASTR + seg * 16,
                     Ab + (long)(m0 + row) * KP + k0 + seg * 8);
            }
            loadB(tn, db);
        };

#pragma unroll
        for (int t = 0; t < 3; t++) { load_tile(t, sb0 + t * BUFSZ); CP_COMMIT(); }

        for (int t = 0; t < KTILES; t++) {
            asm volatile("cp.async.wait_group 2;" ::: "memory");
            __syncthreads();
            if (t + 3 < KTILES)
                load_tile(t + 3, sb0 + ((t + 3) & 3) * BUFSZ);
            CP_COMMIT();

            const uint32_t ab = sb0 + (t & 3) * BUFSZ;
            const uint32_t bb = ab + BOFF;
#pragma unroll
            for (int ks = 0; ks < 2; ks++) {
                uint32_t ar[2][4], brT[4][4];
#pragma unroll
                for (int i = 0; i < 2; i++)
                    LDSM4(ar[i][0], ar[i][1], ar[i][2], ar[i][3],
                          ab + (wm + i * 16 + a_r) * ASTR + ks * 32 + a_ko);
#pragma unroll
                for (int j = 0; j < 4; j++)
                    LDSM4T(brT[j][0], brT[j][1], brT[j][2], brT[j][3],
                           bb + (ks * 16 + bt_k) * BSTR + wn * 2 + j * 32 + bt_n);
#pragma unroll
                for (int i = 0; i < 2; i++)
#pragma unroll
                    for (int jn = 0; jn < 8; jn++) {
                        int jj = jn >> 1, pr = jn & 1;
                        MMA16816(acc[i][jn], ar[i], brT[jj][pr * 2], brT[jj][pr * 2 + 1]);
                    }
            }
        }

#pragma unroll
        for (int i = 0; i < 2; i++) {
#pragma unroll
            for (int jn = 0; jn < 8; jn++) {
                int r = m0 + wm + i * 16 + (lane >> 2);
                int cc = n0 + wn + jn * 8 + 2 * (lane & 3);
                float2 v0 = make_float2(acc[i][jn][0], acc[i][jn][1]);
                float2 v1 = make_float2(acc[i][jn][2], acc[i][jn][3]);
                *(float2*)(Cb + (long)r * HW + cc)       = v0;
                *(float2*)(Cb + (long)(r + 8) * HW + cc) = v1;
            }
        }
    }
}

// ---------------- split X into bf16 hi/lo planes (same [c][n] layout) ----------------
__global__ __launch_bounds__(256) void splitX_k(const float* __restrict__ src,
                                                __nv_bfloat16* __restrict__ dhi,
                                                __nv_bfloat16* __restrict__ dlo)
{
    long i4 = ((long)blockIdx.x * 256 + threadIdx.x) << 2;
    float4 v = *(const float4*)(src + i4);
    float hx = __bfloat162float(__float2bfloat16(v.x));
    float hy = __bfloat162float(__float2bfloat16(v.y));
    float hz = __bfloat162float(__float2bfloat16(v.z));
    float hw_ = __bfloat162float(__float2bfloat16(v.w));
    uint2 ph = make_uint2(pkbf(v.x, v.y), pkbf(v.z, v.w));
    uint2 pl = make_uint2(pkbf(v.x - hx, v.y - hy), pkbf(v.z - hz, v.w - hw_));
    *(uint2*)(dhi + i4) = ph;
    *(uint2*)(dlo + i4) = pl;
}

// ---------------- split A-side: src fp32 [Msrc][192] -> dst bf16 (hi|hi|lo) ------
__global__ __launch_bounds__(256) void splitA_k(const float* __restrict__ src,
                                                __nv_bfloat16* __restrict__ dst,
                                                int Msrc, long sSrc, long sDst)
{
    int b = blockIdx.y;
    int idx = blockIdx.x * 256 + threadIdx.x;
    int m = idx / KP, k = idx - m * KP;
    int sel = k / 192, cc = k - sel * 192;
    __nv_bfloat16 o = __float2bfloat16(0.f);
    if (m < Msrc) {
        float v = src[(long)b * sSrc + (long)m * 192 + cc];
        __nv_bfloat16 hi = __float2bfloat16(v);
        o = (sel < 2) ? hi : __float2bfloat16(v - __bfloat162float(hi));
    }
    dst[(long)b * sDst + idx] = o;
}

// ---------------- depthwise 3x3 tiled: 2 output rows x 4 cols per thread --------------------
__global__ __launch_bounds__(256) void dwconv_k(const float* __restrict__ wdw)
{
    __shared__ float s[18][128];
    int blk   = blockIdx.x;
    int strip = blk & 7;                    // 8 strips of 16 rows
    long bc   = blk >> 3;                   // b*C3 + ch
    int ch    = (int)(bc % C3);
    int b     = (int)(bc / C3);
    const float* in = g_qkv + (bc << 14);
    const int tid = threadIdx.x;

    float w[9];
#pragma unroll
    for (int i = 0; i < 9; i++) w[i] = __ldg(wdw + ch * 9 + i);

    const int y0 = strip << 4;
    for (int i = tid; i < 576; i += 256) {  // 18 rows x 32 float4
        int r = i >> 5, c4 = (i & 31) << 2;
        int gy = y0 - 1 + r;
        float4 v = (gy >= 0 && gy < IMH)
                     ? *(const float4*)(in + gy * IMW + c4)
                     : make_float4(0.f, 0.f, 0.f, 0.f);
        *(float4*)&s[r][c4] = v;
    }
    __syncthreads();

    const int ty = (tid >> 5) << 1;         // 0,2,..,14
    const int x0 = (tid & 31) << 2;
    float o0[4] = {0.f, 0.f, 0.f, 0.f};
    float o1[4] = {0.f, 0.f, 0.f, 0.f};
#pragma unroll
    for (int r = 0; r < 4; r++) {
        const float* sr = s[ty + r];
        float vm = (x0 > 0)   ? sr[x0 - 1] : 0.f;
        float v0 = sr[x0],     v1 = sr[x0 + 1];
        float v2 = sr[x0 + 2], v3 = sr[x0 + 3];
        float vp = (x0 < 124) ? sr[x0 + 4] : 0.f;
        if (r < 3) {
            float wa = w[r * 3], wb = w[r * 3 + 1], wc = w[r * 3 + 2];
            o0[0] = fmaf(wa, vm, fmaf(wb, v0, fmaf(wc, v1, o0[0])));
            o0[1] = fmaf(wa, v0, fmaf(wb, v1, fmaf(wc, v2, o0[1])));
            o0[2] = fmaf(wa, v1, fmaf(wb, v2, fmaf(wc, v3, o0[2])));
            o0[3] = fmaf(wa, v2, fmaf(wb, v3, fmaf(wc, vp, o0[3])));
        }
        if (r >= 1) {
            float wa = w[(r - 1) * 3], wb = w[(r - 1) * 3 + 1], wc = w[(r - 1) * 3 + 2];
            o1[0] = fmaf(wa, vm, fmaf(wb, v0, fmaf(wc, v1, o1[0])));
            o1[1] = fmaf(wa, v0, fmaf(wb, v1, fmaf(wc, v2, o1[1])));
            o1[2] = fmaf(wa, v1, fmaf(wb, v2, fmaf(wc, v3, o1[2])));
            o1[3] = fmaf(wa, v2, fmaf(wb, v3, fmaf(wc, vp, o1[3])));
        }
    }
    int sp0 = (y0 + ty) * IMW + x0;
    int sp1 = sp0 + IMW;
    if (ch < 2 * DIMC) {
        float* op = g_dw + (bc << 14);
        *(float4*)(op + sp0) = make_float4(o0[0], o0[1], o0[2], o0[3]);
        *(float4*)(op + sp1) = make_float4(o1[0], o1[1], o1[2], o1[3]);
    } else {
        long voff = ((long)b * DIMC + (ch - 2 * DIMC)) * HW;
        float h00 = __bfloat162float(__float2bfloat16(o0[0]));
        float h01 = __bfloat162float(__float2bfloat16(o0[1]));
        float h02 = __bfloat162float(__float2bfloat16(o0[2]));
        float h03 = __bfloat162float(__float2bfloat16(o0[3]));
        float h10 = __bfloat162float(__float2bfloat16(o1[0]));
        float h11 = __bfloat162float(__float2bfloat16(o1[1]));
        float h12 = __bfloat162float(__float2bfloat16(o1[2]));
        float h13 = __bfloat162float(__float2bfloat16(o1[3]));
        *(uint2*)(g_vhi + voff + sp0) = make_uint2(pkbf(o0[0], o0[1]), pkbf(o0[2], o0[3]));
        *(uint2*)(g_vhi + voff + sp1) = make_uint2(pkbf(o1[0], o1[1]), pkbf(o1[2], o1[3]));
        *(uint2*)(g_vlo + voff + sp0) = make_uint2(pkbf(o0[0] - h00, o0[1] - h01),
                                                   pkbf(o0[2] - h02, o0[3] - h03));
        *(uint2*)(g_vlo + voff + sp1) = make_uint2(pkbf(o1[0] - h10, o1[1] - h11),
                                                   pkbf(o1[2] - h12, o1[3] - h13));
    }
}

// ---------------- attn partials, 2x3 register-blocked, 96 threads (3 warps exactly) ---------
__global__ __launch_bounds__(96) void attnpart_k()
{
    int bh = blockIdx.x;
    int split = blockIdx.y;
    int b = bh >> 3, h = bh & 7;
    const int tid = threadIdx.x;            // 0..95
    const int cb = tid >> 3, db = tid & 7;  // 12 x 8 blocks
    const int c0 = cb << 1, d0 = db * 3;    // 2 q-rows, 3 k-rows
    __shared__ float qs[24 * 68];
    __shared__ float ks[24 * 68];
    const float* qbase = g_dw + ((long)b * C3 + h * HD) * HW;
    const float* kbase = qbase + (long)DIMC * HW;
    float4 a_[2][3];
#pragma unroll
    for (int i = 0; i < 2; i++)
#pragma unroll
        for (int j = 0; j < 3; j++) a_[i][j] = make_float4(0.f, 0.f, 0.f, 0.f);
    float4 qq[2] = {{0,0,0,0}, {0,0,0,0}};
    float4 kk[3] = {{0,0,0,0}, {0,0,0,0}, {0,0,0,0}};
    const bool doq = (db == 0), dok = (cb == 0);
    int n0 = split * (HW / NSPLIT);
    int n1 = n0 + (HW / NSPLIT);
    for (; n0 < n1; n0 += 64) {
        for (int i = tid; i < 768; i += 96) {
            int m = (i >= 384);
            int j = i - (m ? 384 : 0);
            int r = j >> 4, c4 = j & 15;
            const float* src = (m ? kbase : qbase) + (long)r * HW + n0 + (c4 << 2);
            float* dst = (m ? ks : qs) + r * 68 + (c4 << 2);
            *(float4*)dst = *(const float4*)src;
        }
        __syncthreads();
#pragma unroll
        for (int j = 0; j < 16; j++) {
            float4 q0 = *(const float4*)&qs[ c0      * 68 + (j << 2)];
            float4 q1 = *(const float4*)&qs[(c0 + 1) * 68 + (j << 2)];
            float4 k0 = *(const float4*)&ks[ d0      * 68 + (j << 2)];
            float4 k1 = *(const float4*)&ks[(d0 + 1) * 68 + (j << 2)];
            float4 k2 = *(const float4*)&ks[(d0 + 2) * 68 + (j << 2)];
            float4 qv[2] = {q0, q1};
            float4 kv[3] = {k0, k1, k2};
#pragma unroll
            for (int i = 0; i < 2; i++)
#pragma unroll
                for (int jj = 0; jj < 3; jj++) {
                    a_[i][jj].x = fmaf(qv[i].x, kv[jj].x, a_[i][jj].x);
                    a_[i][jj].y = fmaf(qv[i].y, kv[jj].y, a_[i][jj].y);
                    a_[i][jj].z = fmaf(qv[i].z, kv[jj].z, a_[i][jj].z);
                    a_[i][jj].w = fmaf(qv[i].w, kv[jj].w, a_[i][jj].w);
                }
            if (doq) {
#pragma unroll
                for (int i = 0; i < 2; i++) {
                    qq[i].x = fmaf(qv[i].x, qv[i].x, qq[i].x);
                    qq[i].y = fmaf(qv[i].y, qv[i].y, qq[i].y);
                    qq[i].z = fmaf(qv[i].z, qv[i].z, qq[i].z);
                    qq[i].w = fmaf(qv[i].w, qv[i].w, qq[i].w);
                }
            }
            if (dok) {
#pragma unroll
                for (int jj = 0; jj < 3; jj++) {
                    kk[jj].x = fmaf(kv[jj].x, kv[jj].x, kk[jj].x);
                    kk[jj].y = fmaf(kv[jj].y, kv[jj].y, kk[jj].y);
                    kk[jj].z = fmaf(kv[jj].z, kv[jj].z, kk[jj].z);
                    kk[jj].w = fmaf(kv[jj].w, kv[jj].w, kk[jj].w);
                }
            }
        }
        __syncthreads();
    }
    long pbase = ((long)split * 64 + bh);
    float* ap = g_attn_part + pbase * 576;
#pragma unroll
    for (int i = 0; i < 2; i++)
#pragma unroll
        for (int jj = 0; jj < 3; jj++)
            ap[(c0 + i) * 24 + d0 + jj] =
                (a_[i][jj].x + a_[i][jj].y) + (a_[i][jj].z + a_[i][jj].w);
    float* np = g_np + pbase * 48;
    if (doq) {
        np[c0]     = (qq[0].x + qq[0].y) + (qq[0].z + qq[0].w);
        np[c0 + 1] = (qq[1].x + qq[1].y) + (qq[1].z + qq[1].w);
    }
    if (dok) {
#pragma unroll
        for (int jj = 0; jj < 3; jj++)
            np[24 + d0 + jj] = (kk[jj].x + kk[jj].y) + (kk[jj].z + kk[jj].w);
    }
}

// ---------------- combine splits + norms, scale, softmax ----------------
__global__ __launch_bounds__(576) void softmax_k(const float* __restrict__ temp)
{
    int bh = blockIdx.x; int h = bh & 7;
    int tid = threadIdx.x;
    int c = tid / 24, d = tid - c * 24;
    float s = 0.f;
#pragma unroll
    for (int sp = 0; sp < NSPLIT; sp++)
        s += g_attn_part[((long)sp * 64 + bh) * 576 + tid];
    __shared__ float sinv[48];
    if (tid < 48) {
        float t = 0.f;
#pragma unroll
        for (int sp = 0; sp < NSPLIT; sp++)
            t += g_np[((long)sp * 64 + bh) * 48 + tid];
        sinv[tid] = 1.0f / fmaxf(sqrtf(t), 1e-12f);
    }
    __syncthreads();
    __shared__ float as_[24][25];
    as_[c][d] = s * sinv[c] * sinv[24 + d] * temp[h];
    __syncthreads();
    __shared__ float rowmax[24], rowsum[24];
    if (tid < 24) {
        float m = -1e30f;
#pragma unroll
        for (int j = 0; j < 24; j++) m = fmaxf(m, as_[tid][j]);
        float sum = 0.f;
#pragma unroll
        for (int j = 0; j < 24; j++) sum += expf(as_[tid][j] - m);
        rowmax[tid] = m; rowsum[tid] = sum;
    }
    __syncthreads();
    g_attn[(long)bh * 576 + tid] = expf(as_[c][d] - rowmax[c]) / rowsum[c];
}

// ---------------- M_b = W_out * blockdiag(attn_b), emitted directly as bf16 A' (hi|hi|lo) ----
__global__ __launch_bounds__(256) void buildM_k(const float* __restrict__ wout)
{
    int idx = blockIdx.x * 256 + threadIdx.x;   // 0..36863 = o*192 + (h*24+d)
    int b = blockIdx.y;
    int o  = idx / DIMC, kk = idx - o * DIMC;
    int h  = kk / HD,    d  = kk - h * HD;
    const float* wrow = wout + o * DIMC + h * HD;
    const float* arow = g_attn + (long)(b * NH + h) * (HD * HD) + d;
    float s = 0.f;
#pragma unroll
    for (int cc = 0; cc < HD; cc++)
        s = fmaf(wrow[cc], arow[cc * HD], s);
    __nv_bfloat16 hi = __float2bfloat16(s);
    __nv_bfloat16 lo = __float2bfloat16(s - __bfloat162float(hi));
    __nv_bfloat16* dst = g_m2 + (long)b * (DIMC * KP) + (long)o * KP + kk;
    dst[0]   = hi;
    dst[192] = hi;
    dst[384] = lo;
}

// ---------------- launch ----------------
extern "C" void kernel_launch(void* const* d_in, const int* in_sizes, int n_in,
                              void* d_out, int out_size)
{
    const float* x      = (const float*)d_in[0];
    const float* w_qkv  = (const float*)d_in[1];
    const float* w_dw   = (const float*)d_in[2];
    const float* w_out  = (const float*)d_in[3];
    const float* temp   = (const float*)d_in[4];
    float* out = (float*)d_out;

    float *p_qkv;
    __nv_bfloat16 *p_w1, *p_m2, *p_xhi, *p_xlo, *p_vhi, *p_vlo;
    cudaGetSymbolAddress((void**)&p_qkv, g_qkv);
    cudaGetSymbolAddress((void**)&p_w1,  g_w1);
    cudaGetSymbolAddress((void**)&p_m2,  g_m2);
    cudaGetSymbolAddress((void**)&p_xhi, g_xhi);
    cudaGetSymbolAddress((void**)&p_xlo, g_xlo);
    cudaGetSymbolAddress((void**)&p_vhi, g_vhi);
    cudaGetSymbolAddress((void**)&p_vlo, g_vlo);

    cudaFuncSetAttribute(hmma_gemm, cudaFuncAttributeMaxDynamicSharedMemorySize, SMEM_G);

    // 0) A' = [Whi|Whi|Wlo] for gemm1
    splitA_k<<<dim3(C3 * KP / 256, 1), 256>>>(w_qkv, p_w1, C3, 0L, 0L);

    // 1) X -> bf16 hi/lo planes (no transpose needed)
    splitX_k<<<(BATCH * DIMC * HW) / 1024, 256>>>(x, p_xhi, p_xlo);

    // 2) qkv = W_qkv @ X: y = 4 full 128-tiles + 1 remainder 64-tile, ONE launch
    hmma_gemm<<<dim3(HW / 128, 5, BATCH), 128, SMEM_G>>>(
        p_w1, p_xhi, p_xlo, p_qkv, C3, 0L, (long)DIMC * HW, (long)C3 * HW);

    // 3) depthwise 3x3 (tiled, 2 rows/thread); V channels emit bf16 hi/lo planes
    dwconv_k<<<BATCH * C3 * 8, 256>>>(w_dw);

    // 4) attn partials + fused norms (split-K, deterministic)
    attnpart_k<<<dim3(BATCH * NH, NSPLIT), 96>>>();

    // 5) combine + scale + softmax
    softmax_k<<<BATCH * NH, 576>>>(temp);

    // 6) M_b = W_out * blockdiag(attn_b) -> bf16 A' directly
    buildM_k<<<dim3((DIMC * DIMC) / 256, BATCH), 256>>>(w_out);

    // 7) out = M_b @ V: y = 1 full 128-tile + 1 remainder 64-tile, ONE launch
    hmma_gemm<<<dim3(HW / 128, 2, BATCH), 128, SMEM_G>>>(
        p_m2, p_vhi, p_vlo, out, DIMC, (long)DIMC * KP, (long)DIMC * HW, (long)DIMC * HW);
}

// round 16
// speedup vs baseline: 1.1027x; 1.0403x over previous
#include <cuda_runtime.h>
#include <cuda_bf16.h>
#include <math.h>
#include <stdint.h>

#define BATCH 8
#define DIMC  192
#define C3    576
#define NH    8
#define HD    24
#define IMH   128
#define IMW   128
#define HW    (IMH*IMW)
#define NSPLIT 32
#define KPA   384          // A row length: [hi 192 | lo 192]
#define NCHUNK 6           // k-chunks of 32

// ---------------- scratch (static __device__, zero-initialized) ----------------
static __device__ float g_qkv[BATCH * C3 * HW];                // 1x1 conv output (fp32)
static __device__ float g_dw [BATCH * C3 * HW];                // depthwise out (q,k fp32)
static __device__ float g_attn_part[NSPLIT * BATCH * NH * HD * HD];
static __device__ float g_np[NSPLIT * BATCH * NH * 2 * HD];
static __device__ float g_attn[BATCH * NH * HD * HD];
static __device__ __nv_bfloat16 g_w1[C3 * KPA];                // A gemm1 [576][hi|lo]
static __device__ __nv_bfloat16 g_m2[BATCH * DIMC * KPA];      // A gemm2 [192][hi|lo]
static __device__ __nv_bfloat16 g_xhi[BATCH * DIMC * HW];      // X hi plane [c][n]
static __device__ __nv_bfloat16 g_xlo[BATCH * DIMC * HW];      // X lo plane [c][n]
static __device__ __nv_bfloat16 g_vhi[BATCH * DIMC * HW];      // V hi plane [c][n]
static __device__ __nv_bfloat16 g_vlo[BATCH * DIMC * HW];      // V lo plane [c][n]

// ---------------- PTX helpers (sm_80-level only) ----------------
__device__ __forceinline__ uint32_t s2u(const void* p) {
    uint32_t a;
    asm("{ .reg .u64 t; cvta.to.shared.u64 t, %1; cvt.u32.u64 %0, t; }" : "=r"(a) : "l"(p));
    return a;
}
#define CP16(d, s) asm volatile("cp.async.cg.shared.global [%0], [%1], 16;" :: "r"(d), "l"(s))
#define CP_COMMIT() asm volatile("cp.async.commit_group;" ::: "memory")
#define LDSM4(r0, r1, r2, r3, a) \
    asm volatile("ldmatrix.sync.aligned.m8n8.x4.shared.b16 {%0,%1,%2,%3}, [%4];" \
                 : "=r"(r0), "=r"(r1), "=r"(r2), "=r"(r3) : "r"(a))
#define LDSM4T(r0, r1, r2, r3, a) \
    asm volatile("ldmatrix.sync.aligned.m8n8.x4.trans.shared.b16 {%0,%1,%2,%3}, [%4];" \
                 : "=r"(r0), "=r"(r1), "=r"(r2), "=r"(r3) : "r"(a))
#define MMA16816(d, a, b0, b1) \
    asm volatile("mma.sync.aligned.m16n8k16.row.col.f32.bf16.bf16.f32 " \
                 "{%0,%1,%2,%3}, {%4,%5,%6,%7}, {%8,%9}, {%0,%1,%2,%3};" \
                 : "+f"((d)[0]), "+f"((d)[1]), "+f"((d)[2]), "+f"((d)[3]) \
                 : "r"((a)[0]), "r"((a)[1]), "r"((a)[2]), "r"((a)[3]), \
                   "r"(b0), "r"(b1))

__device__ __forceinline__ uint32_t pkbf(float a, float b) {
    return ((uint32_t)__bfloat16_as_ushort(__float2bfloat16(b)) << 16) |
           (uint32_t)__bfloat16_as_ushort(__float2bfloat16(a));
}

// ===== merged GEMM, chunked split-bf16: per chunk {Ahi,Alo,Bhi,Blo}, 3 MMA passes =====
// full tiles BM=128 (warp 64x64), remainder BM=64 (warp 32x64); BN=128, BK=32
#define ASTR   80                     // A smem row stride
#define BSTR   272                    // B smem row stride
#define AOFF_LO (128 * ASTR)          // 10240
#define BHOFF   (2 * 128 * ASTR)      // 20480
#define BLOFF   (BHOFF + 32 * BSTR)   // 29184
#define BUFSZ   (BLOFF + 32 * BSTR)   // 37888
#define SMEM_G  (2 * BUFSZ)           // 75776
__global__ __launch_bounds__(128, 2) void hmma_gemm(
    const __nv_bfloat16* __restrict__ A,
    const __nv_bfloat16* __restrict__ BHI, const __nv_bfloat16* __restrict__ BLO,
    float* __restrict__ C, int Mtot, long sA, long sBp, long sC)
{
    extern __shared__ __align__(16) char smdyn[];
    const uint32_t sb0 = s2u(smdyn);
    const int tid = threadIdx.x, lane = tid & 31, wid = tid >> 5;
    const int n0 = blockIdx.x << 7;
    const int m0 = blockIdx.y << 7;
    const bool full = (Mtot - m0) >= 128;   // uniform per CTA
    const __nv_bfloat16* Ab  = A   + (long)blockIdx.z * sA;
    const __nv_bfloat16* Bhi = BHI + (long)blockIdx.z * sBp;
    const __nv_bfloat16* Blo = BLO + (long)blockIdx.z * sBp;
    float* Cb = C + (long)blockIdx.z * sC;

    const int a_r  = (lane & 7) + ((lane >> 3) & 1) * 8;
    const int a_ko = (lane >> 4) * 16;
    const int bt_k = (lane & 7) + (((lane >> 3) & 1) << 3);
    const int bt_n = (lane >> 4) * 16;
    const int wn = (wid & 1) << 6;      // 0 / 64 (both paths)

    auto loadB = [&](int j, uint32_t db) {
#pragma unroll
        for (int it = 0; it < 4; it++) {
            int row = (tid >> 4) + it * 8, seg = tid & 15;
            CP16(db + BHOFF + row * BSTR + seg * 16,
                 Bhi + (long)(j * 32 + row) * HW + n0 + seg * 8);
            CP16(db + BLOFF + row * BSTR + seg * 16,
                 Blo + (long)(j * 32 + row) * HW + n0 + seg * 8);
        }
    };

    if (full) {
        const int wm = (wid >> 1) << 6;     // 0 / 64
        float acc[4][8][4];
#pragma unroll
        for (int i = 0; i < 4; i++)
#pragma unroll
            for (int j = 0; j < 8; j++)
#pragma unroll
                for (int v = 0; v < 4; v++) acc[i][j][v] = 0.f;

        auto load_stage = [&](int j, uint32_t db) {
#pragma unroll
            for (int it = 0; it < 4; it++) {
                int row = (tid >> 2) + it * 32, seg = tid & 3;
                const __nv_bfloat16* arow = Ab + (long)(m0 + row) * KPA + j * 32 + seg * 8;
                CP16(db + row * ASTR + seg * 16, arow);
                CP16(db + AOFF_LO + row * ASTR + seg * 16, arow + 192);
            }
            loadB(j, db);
        };

        auto mma_pass = [&](uint32_t ab, uint32_t bb) {
#pragma unroll
            for (int ks = 0; ks < 2; ks++) {
                uint32_t ar[4][4], brT[4][4];
#pragma unroll
                for (int i = 0; i < 4; i++)
                    LDSM4(ar[i][0], ar[i][1], ar[i][2], ar[i][3],
                          ab + (wm + i * 16 + a_r) * ASTR + ks * 32 + a_ko);
#pragma unroll
                for (int j = 0; j < 4; j++)
                    LDSM4T(brT[j][0], brT[j][1], brT[j][2], brT[j][3],
                           bb + (ks * 16 + bt_k) * BSTR + wn * 2 + j * 32 + bt_n);
#pragma unroll
                for (int i = 0; i < 4; i++)
#pragma unroll
                    for (int jn = 0; jn < 8; jn++) {
                        int jj = jn >> 1, pr = jn & 1;
                        MMA16816(acc[i][jn], ar[i], brT[jj][pr * 2], brT[jj][pr * 2 + 1]);
                    }
            }
        };

        load_stage(0, sb0); CP_COMMIT();
        for (int j = 0; j < NCHUNK; j++) {
            asm volatile("cp.async.wait_group 0;" ::: "memory");
            __syncthreads();
            if (j + 1 < NCHUNK)
                load_stage(j + 1, sb0 + ((j + 1) & 1) * BUFSZ);
            CP_COMMIT();
            uint32_t base = sb0 + (j & 1) * BUFSZ;
            mma_pass(base,           base + BHOFF);   // hi*hi
            mma_pass(base,           base + BLOFF);   // hi*lo
            mma_pass(base + AOFF_LO, base + BHOFF);   // lo*hi
        }

#pragma unroll
        for (int i = 0; i < 4; i++) {
#pragma unroll
            for (int jn = 0; jn < 8; jn++) {
                int r = m0 + wm + i * 16 + (lane >> 2);
                int cc = n0 + wn + jn * 8 + 2 * (lane & 3);
                float2 v0 = make_float2(acc[i][jn][0], acc[i][jn][1]);
                float2 v1 = make_float2(acc[i][jn][2], acc[i][jn][3]);
                *(float2*)(Cb + (long)r * HW + cc)       = v0;
                *(float2*)(Cb + (long)(r + 8) * HW + cc) = v1;
            }
        }
    } else {
        // 64-row remainder tile: warp tile 32x64
        const int wm = (wid >> 1) << 5;     // 0 / 32
        float acc[2][8][4];
#pragma unroll
        for (int i = 0; i < 2; i++)
#pragma unroll
            for (int j = 0; j < 8; j++)
#pragma unroll
                for (int v = 0; v < 4; v++) acc[i][j][v] = 0.f;

        auto load_stage = [&](int j, uint32_t db) {
#pragma unroll
            for (int it = 0; it < 2; it++) {
                int row = (tid >> 2) + it * 32, seg = tid & 3;
                const __nv_bfloat16* arow = Ab + (long)(m0 + row) * KPA + j * 32 + seg * 8;
                CP16(db + row * ASTR + seg * 16, arow);
                CP16(db + AOFF_LO + row * ASTR + seg * 16, arow + 192);
            }
            loadB(j, db);
        };

        auto mma_pass = [&](uint32_t ab, uint32_t bb) {
#pragma unroll
            for (int ks = 0; ks < 2; ks++) {
                uint32_t ar[2][4], brT[4][4];
#pragma unroll
                for (int i = 0; i < 2; i++)
                    LDSM4(ar[i][0], ar[i][1], ar[i][2], ar[i][3],
                          ab + (wm + i * 16 + a_r) * ASTR + ks * 32 + a_ko);
#pragma unroll
                for (int j = 0; j < 4; j++)
                    LDSM4T(brT[j][0], brT[j][1], brT[j][2], brT[j][3],
                           bb + (ks * 16 + bt_k) * BSTR + wn * 2 + j * 32 + bt_n);
#pragma unroll
                for (int i = 0; i < 2; i++)
#pragma unroll
                    for (int jn = 0; jn < 8; jn++) {
                        int jj = jn >> 1, pr = jn & 1;
                        MMA16816(acc[i][jn], ar[i], brT[jj][pr * 2], brT[jj][pr * 2 + 1]);
                    }
            }
        };

        load_stage(0, sb0); CP_COMMIT();
        for (int j = 0; j < NCHUNK; j++) {
            asm volatile("cp.async.wait_group 0;" ::: "memory");
            __syncthreads();
            if (j + 1 < NCHUNK)
                load_stage(j + 1, sb0 + ((j + 1) & 1) * BUFSZ);
            CP_COMMIT();
            uint32_t base = sb0 + (j & 1) * BUFSZ;
            mma_pass(base,           base + BHOFF);
            mma_pass(base,           base + BLOFF);
            mma_pass(base + AOFF_LO, base + BHOFF);
        }

#pragma unroll
        for (int i = 0; i < 2; i++) {
#pragma unroll
            for (int jn = 0; jn < 8; jn++) {
                int r = m0 + wm + i * 16 + (lane >> 2);
                int cc = n0 + wn + jn * 8 + 2 * (lane & 3);
                float2 v0 = make_float2(acc[i][jn][0], acc[i][jn][1]);
                float2 v1 = make_float2(acc[i][jn][2], acc[i][jn][3]);
                *(float2*)(Cb + (long)r * HW + cc)       = v0;
                *(float2*)(Cb + (long)(r + 8) * HW + cc) = v1;
            }
        }
    }
}

// ---------------- split X into bf16 hi/lo planes (same [c][n] layout) ----------------
__global__ __launch_bounds__(256) void splitX_k(const float* __restrict__ src,
                                                __nv_bfloat16* __restrict__ dhi,
                                                __nv_bfloat16* __restrict__ dlo)
{
    long i4 = ((long)blockIdx.x * 256 + threadIdx.x) << 2;
    float4 v = *(const float4*)(src + i4);
    float hx = __bfloat162float(__float2bfloat16(v.x));
    float hy = __bfloat162float(__float2bfloat16(v.y));
    float hz = __bfloat162float(__float2bfloat16(v.z));
    float hw_ = __bfloat162float(__float2bfloat16(v.w));
    uint2 ph = make_uint2(pkbf(v.x, v.y), pkbf(v.z, v.w));
    uint2 pl = make_uint2(pkbf(v.x - hx, v.y - hy), pkbf(v.z - hz, v.w - hw_));
    *(uint2*)(dhi + i4) = ph;
    *(uint2*)(dlo + i4) = pl;
}

// ---------------- split A-side: src fp32 [Msrc][192] -> dst bf16 [Msrc][hi|lo] ------
__global__ __launch_bounds__(256) void splitA_k(const float* __restrict__ src,
                                                __nv_bfloat16* __restrict__ dst,
                                                int Msrc)
{
    int idx = blockIdx.x * 256 + threadIdx.x;   // over Msrc*192
    int m = idx / DIMC, cc = idx - m * DIMC;
    float v = src[idx];
    __nv_bfloat16 hi = __float2bfloat16(v);
    dst[(long)m * KPA + cc]       = hi;
    dst[(long)m * KPA + 192 + cc] = __float2bfloat16(v - __bfloat162float(hi));
}

// ---------------- depthwise 3x3 tiled: 2 output rows x 4 cols per thread --------------------
__global__ __launch_bounds__(256) void dwconv_k(const float* __restrict__ wdw)
{
    __shared__ float s[18][128];
    int blk   = blockIdx.x;
    int strip = blk & 7;                    // 8 strips of 16 rows
    long bc   = blk >> 3;                   // b*C3 + ch
    int ch    = (int)(bc % C3);
    int b     = (int)(bc / C3);
    const float* in = g_qkv + (bc << 14);
    const int tid = threadIdx.x;

    float w[9];
#pragma unroll
    for (int i = 0; i < 9; i++) w[i] = __ldg(wdw + ch * 9 + i);

    const int y0 = strip << 4;
    for (int i = tid; i < 576; i += 256) {  // 18 rows x 32 float4
        int r = i >> 5, c4 = (i & 31) << 2;
        int gy = y0 - 1 + r;
        float4 v = (gy >= 0 && gy < IMH)
                     ? *(const float4*)(in + gy * IMW + c4)
                     : make_float4(0.f, 0.f, 0.f, 0.f);
        *(float4*)&s[r][c4] = v;
    }
    __syncthreads();

    const int ty = (tid >> 5) << 1;         // 0,2,..,14
    const int x0 = (tid & 31) << 2;
    float o0[4] = {0.f, 0.f, 0.f, 0.f};
    float o1[4] = {0.f, 0.f, 0.f, 0.f};
#pragma unroll
    for (int r = 0; r < 4; r++) {
        const float* sr = s[ty + r];
        float vm = (x0 > 0)   ? sr[x0 - 1] : 0.f;
        float v0 = sr[x0],     v1 = sr[x0 + 1];
        float v2 = sr[x0 + 2], v3 = sr[x0 + 3];
        float vp = (x0 < 124) ? sr[x0 + 4] : 0.f;
        if (r < 3) {
            float wa = w[r * 3], wb = w[r * 3 + 1], wc = w[r * 3 + 2];
            o0[0] = fmaf(wa, vm, fmaf(wb, v0, fmaf(wc, v1, o0[0])));
            o0[1] = fmaf(wa, v0, fmaf(wb, v1, fmaf(wc, v2, o0[1])));
            o0[2] = fmaf(wa, v1, fmaf(wb, v2, fmaf(wc, v3, o0[2])));
            o0[3] = fmaf(wa, v2, fmaf(wb, v3, fmaf(wc, vp, o0[3])));
        }
        if (r >= 1) {
            float wa = w[(r - 1) * 3], wb = w[(r - 1) * 3 + 1], wc = w[(r - 1) * 3 + 2];
            o1[0] = fmaf(wa, vm, fmaf(wb, v0, fmaf(wc, v1, o1[0])));
            o1[1] = fmaf(wa, v0, fmaf(wb, v1, fmaf(wc, v2, o1[1])));
            o1[2] = fmaf(wa, v1, fmaf(wb, v2, fmaf(wc, v3, o1[2])));
            o1[3] = fmaf(wa, v2, fmaf(wb, v3, fmaf(wc, vp, o1[3])));
        }
    }
    int sp0 = (y0 + ty) * IMW + x0;
    int sp1 = sp0 + IMW;
    if (ch < 2 * DIMC) {
        float* op = g_dw + (bc << 14);
        *(float4*)(op + sp0) = make_float4(o0[0], o0[1], o0[2], o0[3]);
        *(float4*)(op + sp1) = make_float4(o1[0], o1[1], o1[2], o1[3]);
    } else {
        long voff = ((long)b * DIMC + (ch - 2 * DIMC)) * HW;
        float h00 = __bfloat162float(__float2bfloat16(o0[0]));
        float h01 = __bfloat162float(__float2bfloat16(o0[1]));
        float h02 = __bfloat162float(__float2bfloat16(o0[2]));
        float h03 = __bfloat162float(__float2bfloat16(o0[3]));
        float h10 = __bfloat162float(__float2bfloat16(o1[0]));
        float h11 = __bfloat162float(__float2bfloat16(o1[1]));
        float h12 = __bfloat162float(__float2bfloat16(o1[2]));
        float h13 = __bfloat162float(__float2bfloat16(o1[3]));
        *(uint2*)(g_vhi + voff + sp0) = make_uint2(pkbf(o0[0], o0[1]), pkbf(o0[2], o0[3]));
        *(uint2*)(g_vhi + voff + sp1) = make_uint2(pkbf(o1[0], o1[1]), pkbf(o1[2], o1[3]));
        *(uint2*)(g_vlo + voff + sp0) = make_uint2(pkbf(o0[0] - h00, o0[1] - h01),
                                                   pkbf(o0[2] - h02, o0[3] - h03));
        *(uint2*)(g_vlo + voff + sp1) = make_uint2(pkbf(o1[0] - h10, o1[1] - h11),
                                                   pkbf(o1[2] - h12, o1[3] - h13));
    }
}

// ---------------- attn partials, 2x3 register-blocked, 96 threads (3 warps exactly) ---------
__global__ __launch_bounds__(96) void attnpart_k()
{
    int bh = blockIdx.x;
    int split = blockIdx.y;
    int b = bh >> 3, h = bh & 7;
    const int tid = threadIdx.x;            // 0..95
    const int cb = tid >> 3, db = tid & 7;  // 12 x 8 blocks
    const int c0 = cb << 1, d0 = db * 3;    // 2 q-rows, 3 k-rows
    __shared__ float qs[24 * 68];
    __shared__ float ks[24 * 68];
    const float* qbase = g_dw + ((long)b * C3 + h * HD) * HW;
    const float* kbase = qbase + (long)DIMC * HW;
    float4 a_[2][3];
#pragma unroll
    for (int i = 0; i < 2; i++)
#pragma unroll
        for (int j = 0; j < 3; j++) a_[i][j] = make_float4(0.f, 0.f, 0.f, 0.f);
    float4 qq[2] = {{0,0,0,0}, {0,0,0,0}};
    float4 kk[3] = {{0,0,0,0}, {0,0,0,0}, {0,0,0,0}};
    const bool doq = (db == 0), dok = (cb == 0);
    int n0 = split * (HW / NSPLIT);
    int n1 = n0 + (HW / NSPLIT);
    for (; n0 < n1; n0 += 64) {
        for (int i = tid; i < 768; i += 96) {
            int m = (i >= 384);
            int j = i - (m ? 384 : 0);
            int r = j >> 4, c4 = j & 15;
            const float* src = (m ? kbase : qbase) + (long)r * HW + n0 + (c4 << 2);
            float* dst = (m ? ks : qs) + r * 68 + (c4 << 2);
            *(float4*)dst = *(const float4*)src;
        }
        __syncthreads();
#pragma unroll
        for (int j = 0; j < 16; j++) {
            float4 q0 = *(const float4*)&qs[ c0      * 68 + (j << 2)];
            float4 q1 = *(const float4*)&qs[(c0 + 1) * 68 + (j << 2)];
            float4 k0 = *(const float4*)&ks[ d0      * 68 + (j << 2)];
            float4 k1 = *(const float4*)&ks[(d0 + 1) * 68 + (j << 2)];
            float4 k2 = *(const float4*)&ks[(d0 + 2) * 68 + (j << 2)];
            float4 qv[2] = {q0, q1};
            float4 kv[3] = {k0, k1, k2};
#pragma unroll
            for (int i = 0; i < 2; i++)
#pragma unroll
                for (int jj = 0; jj < 3; jj++) {
                    a_[i][jj].x = fmaf(qv[i].x, kv[jj].x, a_[i][jj].x);
                    a_[i][jj].y = fmaf(qv[i].y, kv[jj].y, a_[i][jj].y);
                    a_[i][jj].z = fmaf(qv[i].z, kv[jj].z, a_[i][jj].z);
                    a_[i][jj].w = fmaf(qv[i].w, kv[jj].w, a_[i][jj].w);
                }
            if (doq) {
#pragma unroll
                for (int i = 0; i < 2; i++) {
                    qq[i].x = fmaf(qv[i].x, qv[i].x, qq[i].x);
                    qq[i].y = fmaf(qv[i].y, qv[i].y, qq[i].y);
                    qq[i].z = fmaf(qv[i].z, qv[i].z, qq[i].z);
                    qq[i].w = fmaf(qv[i].w, qv[i].w, qq[i].w);
                }
            }
            if (dok) {
#pragma unroll
                for (int jj = 0; jj < 3; jj++) {
                    kk[jj].x = fmaf(kv[jj].x, kv[jj].x, kk[jj].x);
                    kk[jj].y = fmaf(kv[jj].y, kv[jj].y, kk[jj].y);
                    kk[jj].z = fmaf(kv[jj].z, kv[jj].z, kk[jj].z);
                    kk[jj].w = fmaf(kv[jj].w, kv[jj].w, kk[jj].w);
                }
            }
        }
        __syncthreads();
    }
    long pbase = ((long)split * 64 + bh);
    float* ap = g_attn_part + pbase * 576;
#pragma unroll
    for (int i = 0; i < 2; i++)
#pragma unroll
        for (int jj = 0; jj < 3; jj++)
            ap[(c0 + i) * 24 + d0 + jj] =
                (a_[i][jj].x + a_[i][jj].y) + (a_[i][jj].z + a_[i][jj].w);
    float* np = g_np + pbase * 48;
    if (doq) {
        np[c0]     = (qq[0].x + qq[0].y) + (qq[0].z + qq[0].w);
        np[c0 + 1] = (qq[1].x + qq[1].y) + (qq[1].z + qq[1].w);
    }
    if (dok) {
#pragma unroll
        for (int jj = 0; jj < 3; jj++)
            np[24 + d0 + jj] = (kk[jj].x + kk[jj].y) + (kk[jj].z + kk[jj].w);
    }
}

// ---------------- combine splits + norms, scale, softmax ----------------
__global__ __launch_bounds__(576) void softmax_k(const float* __restrict__ temp)
{
    int bh = blockIdx.x; int h = bh & 7;
    int tid = threadIdx.x;
    int c = tid / 24, d = tid - c * 24;
    float s = 0.f;
#pragma unroll
    for (int sp = 0; sp < NSPLIT; sp++)
        s += g_attn_part[((long)sp * 64 + bh) * 576 + tid];
    __shared__ float sinv[48];
    if (tid < 48) {
        float t = 0.f;
#pragma unroll
        for (int sp = 0; sp < NSPLIT; sp++)
            t += g_np[((long)sp * 64 + bh) * 48 + tid];
        sinv[tid] = 1.0f / fmaxf(sqrtf(t), 1e-12f);
    }
    __syncthreads();
    __shared__ float as_[24][25];
    as_[c][d] = s * sinv[c] * sinv[24 + d] * temp[h];
    __syncthreads();
    __shared__ float rowmax[24], rowsum[24];
    if (tid < 24) {
        float m = -1e30f;
#pragma unroll
        for (int j = 0; j < 24; j++) m = fmaxf(m, as_[tid][j]);
        float sum = 0.f;
#pragma unroll
        for (int j = 0; j < 24; j++) sum += expf(as_[tid][j] - m);
        rowmax[tid] = m; rowsum[tid] = sum;
    }
    __syncthreads();
    g_attn[(long)bh * 576 + tid] = expf(as_[c][d] - rowmax[c]) / rowsum[c];
}

// ---------------- M_b = W_out * blockdiag(attn_b), emitted directly as bf16 A [hi|lo] ----
__global__ __launch_bounds__(256) void buildM_k(const float* __restrict__ wout)
{
    int idx = blockIdx.x * 256 + threadIdx.x;   // 0..36863 = o*192 + (h*24+d)
    int b = blockIdx.y;
    int o  = idx / DIMC, kk = idx - o * DIMC;
    int h  = kk / HD,    d  = kk - h * HD;
    const float* wrow = wout + o * DIMC + h * HD;
    const float* arow = g_attn + (long)(b * NH + h) * (HD * HD) + d;
    float s = 0.f;
#pragma unroll
    for (int cc = 0; cc < HD; cc++)
        s = fmaf(wrow[cc], arow[cc * HD], s);
    __nv_bfloat16 hi = __float2bfloat16(s);
    __nv_bfloat16* dst = g_m2 + (long)b * (DIMC * KPA) + (long)o * KPA + kk;
    dst[0]   = hi;
    dst[192] = __float2bfloat16(s - __bfloat162float(hi));
}

// ---------------- launch ----------------
extern "C" void kernel_launch(void* const* d_in, const int* in_sizes, int n_in,
                              void* d_out, int out_size)
{
    const float* x      = (const float*)d_in[0];
    const float* w_qkv  = (const float*)d_in[1];
    const float* w_dw   = (const float*)d_in[2];
    const float* w_out  = (const float*)d_in[3];
    const float* temp   = (const float*)d_in[4];
    float* out = (float*)d_out;

    float *p_qkv;
    __nv_bfloat16 *p_w1, *p_m2, *p_xhi, *p_xlo, *p_vhi, *p_vlo;
    cudaGetSymbolAddress((void**)&p_qkv, g_qkv);
    cudaGetSymbolAddress((void**)&p_w1,  g_w1);
    cudaGetSymbolAddress((void**)&p_m2,  g_m2);
    cudaGetSymbolAddress((void**)&p_xhi, g_xhi);
    cudaGetSymbolAddress((void**)&p_xlo, g_xlo);
    cudaGetSymbolAddress((void**)&p_vhi, g_vhi);
    cudaGetSymbolAddress((void**)&p_vlo, g_vlo);

    cudaFuncSetAttribute(hmma_gemm, cudaFuncAttributeMaxDynamicSharedMemorySize, SMEM_G);

    // 0) A = [Whi|Wlo] for gemm1
    splitA_k<<<(C3 * DIMC) / 256, 256>>>(w_qkv, p_w1, C3);

    // 1) X -> bf16 hi/lo planes (no transpose needed)
    splitX_k<<<(BATCH * DIMC * HW) / 1024, 256>>>(x, p_xhi, p_xlo);

    // 2) qkv = W_qkv @ X: 4 full 128-tiles + 1 remainder 64-tile, one launch
    hmma_gemm<<<dim3(HW / 128, 5, BATCH), 128, SMEM_G>>>(
        p_w1, p_xhi, p_xlo, p_qkv, C3, 0L, (long)DIMC * HW, (long)C3 * HW);

    // 3) depthwise 3x3 (tiled, 2 rows/thread); V channels emit bf16 hi/lo planes
    dwconv_k<<<BATCH * C3 * 8, 256>>>(w_dw);

    // 4) attn partials + fused norms (split-K, deterministic)
    attnpart_k<<<dim3(BATCH * NH, NSPLIT), 96>>>();

    // 5) combine + scale + softmax
    softmax_k<<<BATCH * NH, 576>>>(temp);

    // 6) M_b = W_out * blockdiag(attn_b) -> bf16 A [hi|lo] directly
    buildM_k<<<dim3((DIMC * DIMC) / 256, BATCH), 256>>>(w_out);

    // 7) out = M_b @ V: 1 full 128-tile + 1 remainder 64-tile, one launch
    hmma_gemm<<<dim3(HW / 128, 2, BATCH), 128, SMEM_G>>>(
        p_m2, p_vhi, p_vlo, out, DIMC, (long)DIMC * KPA, (long)DIMC * HW, (long)DIMC * HW);
}